// round 9
// baseline (speedup 1.0000x reference)
#include <cuda_runtime.h>
#include <cuda_bf16.h>
#include <math.h>
#include <stdint.h>

#define BATCH  4
#define CH     256
#define NGROUP 32
#define HW     4096
#define GEPS   1e-6f
#define STAGES 4

typedef __nv_bfloat16 bf16;

// ---------------- scratch (device globals; no allocation allowed) -------------
__device__ bf16  g_ofT[(size_t)BATCH * HW * CH];   // GN output, transposed [b][i][c]
__device__ bf16  g_q  [(size_t)BATCH * HW * CH];   // Q  [b][i][c]
__device__ bf16  g_k  [(size_t)BATCH * HW * CH];   // K  [b][j][c]
__device__ bf16  g_v  [(size_t)BATCH * CH * HW];   // V  [b][c][j]
__device__ bf16  g_atT[(size_t)BATCH * HW * CH];   // attn out transposed [b][i][c]
__device__ bf16  g_s  [(size_t)BATCH * HW * HW];   // expS bf16 (134MB)
__device__ bf16  g_w16[4 * CH * CH];               // bf16 weights: wq|wk|wv|wp
__device__ float g_l  [BATCH * HW];                // softmax row sums (atomic)
__device__ float g_mean[BATCH * NGROUP];
__device__ float g_rstd[BATCH * NGROUP];

// ---------------- GroupNorm: stats --------------------------------------------
__global__ void __launch_bounds__(256) gn_stats(const float* __restrict__ x) {
    const int bg = blockIdx.x;
    const float* p = x + (size_t)bg * (CH / NGROUP) * HW;
    const int tid = threadIdx.x;

    float s = 0.f, s2 = 0.f;
    const int n4 = (CH / NGROUP) * HW / 4;
    for (int i = tid; i < n4; i += 256) {
        float4 v = ((const float4*)p)[i];
        s  += v.x + v.y + v.z + v.w;
        s2 += v.x * v.x + v.y * v.y + v.z * v.z + v.w * v.w;
    }
    __shared__ float red[64];
    #pragma unroll
    for (int o = 16; o; o >>= 1) {
        s  += __shfl_xor_sync(0xffffffffu, s,  o);
        s2 += __shfl_xor_sync(0xffffffffu, s2, o);
    }
    if ((tid & 31) == 0) { red[tid >> 5] = s; red[32 + (tid >> 5)] = s2; }
    __syncthreads();
    if (tid == 0) {
        float ts = 0.f, ts2 = 0.f;
        #pragma unroll
        for (int w = 0; w < 8; w++) { ts += red[w]; ts2 += red[32 + w]; }
        const float inv_n = 1.0f / ((CH / NGROUP) * HW);
        float mean = ts * inv_n;
        float var  = ts2 * inv_n - mean * mean;
        g_mean[bg] = mean;
        g_rstd[bg] = rsqrtf(var + GEPS);
    }
}

// ---------------- zero the softmax row-sum accumulator --------------------------
__global__ void __launch_bounds__(256) zero_l() {
    g_l[blockIdx.x * 256 + threadIdx.x] = 0.f;
}

// ---------------- GroupNorm apply + transpose -> bf16 OF^T [b][i][c] -----------
__global__ void __launch_bounds__(256) gn_apply_t(const float* __restrict__ x,
                                                  const float* __restrict__ gs,
                                                  const float* __restrict__ gb) {
    __shared__ float tile[32][33];
    const int i0 = blockIdx.x * 32, c0 = blockIdx.y * 32, b = blockIdx.z;
    const int tx = threadIdx.x, ty = threadIdx.y;

    #pragma unroll
    for (int dy = 0; dy < 4; dy++) {
        int c = c0 + ty + dy * 8;
        int bg = b * NGROUP + (c >> 3);
        float r = g_rstd[bg];
        float a = gs[c] * r;
        float t = gb[c] - g_mean[bg] * a;
        float v = x[((size_t)b * CH + c) * HW + i0 + tx];
        tile[ty + dy * 8][tx] = v * a + t;
    }
    __syncthreads();

    const int tid = ty * 32 + tx;
    #pragma unroll
    for (int h = 0; h < 2; h++) {
        int p = tid + h * 256;
        int il = p >> 4, cl = (p & 15) * 2;
        __nv_bfloat162 o;
        o.x = __float2bfloat16_rn(tile[cl][il]);
        o.y = __float2bfloat16_rn(tile[cl + 1][il]);
        *(__nv_bfloat162*)(&g_ofT[((size_t)b * HW + i0 + il) * CH + c0 + cl]) = o;
    }
}

// ---------------- weights -> bf16 ----------------------------------------------
__global__ void __launch_bounds__(256) conv_w(const float* __restrict__ wq,
                                              const float* __restrict__ wk,
                                              const float* __restrict__ wv,
                                              const float* __restrict__ wp) {
    int i = blockIdx.x * 256 + threadIdx.x;
    if (i >= CH * CH) return;
    g_w16[0 * CH * CH + i] = __float2bfloat16_rn(wq[i]);
    g_w16[1 * CH * CH + i] = __float2bfloat16_rn(wk[i]);
    g_w16[2 * CH * CH + i] = __float2bfloat16_rn(wv[i]);
    g_w16[3 * CH * CH + i] = __float2bfloat16_rn(wp[i]);
}

// ---------------- bf16 tensor-core GEMM (mma.sync HMMA, R5 config) --------------
// D[m][n] = scale * sum_k A[m][k]*B[n][k] (+ epilogue)
// A: [M][K] bf16 k-contig, B: [N][K] bf16 k-contig.
// EPI 1: bf16 out*scale + bias[n].  EPI 2: bf16 out*scale + bias[m].
// EPI 4: fp32 out + bias[m] + resid[m][n].
// EPI 5: bf16 out = exp(acc*scale); atomicAdd per-row sums into lptr.
// EPI 6: bf16 out = acc / lptr[row].
// CTA 128x128, BK=32, 8 warps (2m x 4n), warp tile 64x32, 4-stage cp.async.

__device__ __forceinline__ unsigned swz(int m, int c) {  // 16B-chunk index in [128][32]bf16 tile
    return (unsigned)((m << 2) + (c ^ ((m >> 1) & 3)));
}

#define CP16(dst_u32, src_ptr) \
    asm volatile("cp.async.cg.shared.global [%0], [%1], 16;\n" :: "r"(dst_u32), "l"(src_ptr))
#define LDMX4(r0, r1, r2, r3, addr) \
    asm volatile("ldmatrix.sync.aligned.m8n8.x4.shared.b16 {%0,%1,%2,%3}, [%4];\n" \
                 : "=r"(r0), "=r"(r1), "=r"(r2), "=r"(r3) : "r"(addr))
#define MMA16816(c0, c1, c2, c3, a0, a1, a2, a3, b0, b1) \
    asm volatile("mma.sync.aligned.m16n8k16.row.col.f32.bf16.bf16.f32 " \
                 "{%0,%1,%2,%3}, {%4,%5,%6,%7}, {%8,%9}, {%0,%1,%2,%3};\n" \
                 : "+f"(c0), "+f"(c1), "+f"(c2), "+f"(c3) \
                 : "r"(a0), "r"(a1), "r"(a2), "r"(a3), "r"(b0), "r"(b1))
#define COMMIT() asm volatile("cp.async.commit_group;\n")
#define WAITG(n) asm volatile("cp.async.wait_group %0;\n" :: "n"(n))

#define GEMM_SMEM_BYTES (STAGES * 16384)

template<int EPI>
__global__ void __launch_bounds__(256) mma_gemm(
    const bf16* __restrict__ A, const bf16* __restrict__ B,
    void* __restrict__ Dv, int M, int N, int K,
    long long sA, long long sB, long long sD, float scale,
    const float* __restrict__ bias, const float* __restrict__ resid,
    float* __restrict__ lptr = nullptr)
{
    extern __shared__ __align__(16) unsigned char sm[];   // STAGES x [A 8KB | B 8KB]
    const int bz = blockIdx.z;
    A += (size_t)bz * sA;
    B += (size_t)bz * sB;
    const int m0 = blockIdx.y * 128, n0 = blockIdx.x * 128;
    const int tid = threadIdx.x, lane = tid & 31, warp = tid >> 5;
    const int wm = warp >> 2, wn = warp & 3;

    const unsigned smbase = (unsigned)__cvta_generic_to_shared(sm);

    const int lm = tid >> 2, lc = tid & 3;
    const bf16* gA0 = A + (size_t)(m0 + lm)      * K + lc * 8;
    const bf16* gA1 = A + (size_t)(m0 + lm + 64) * K + lc * 8;
    const bf16* gB0 = B + (size_t)(n0 + lm)      * K + lc * 8;
    const bf16* gB1 = B + (size_t)(n0 + lm + 64) * K + lc * 8;
    const unsigned dA0 = swz(lm, lc) * 16u;
    const unsigned dA1 = swz(lm + 64, lc) * 16u;
    const unsigned dB0 = 8192u + swz(lm, lc) * 16u;
    const unsigned dB1 = 8192u + swz(lm + 64, lc) * 16u;

    unsigned aOff[4], bOff[2];
    {
        int r = wm * 64 + (lane & 15);
        int c0 = lane >> 4;
        #pragma unroll
        for (int mt = 0; mt < 4; mt++) aOff[mt] = swz(r + mt * 16, c0) * 16u;
    }
    {
        int r = wn * 32 + ((lane >> 4) << 3) + (lane & 7);
        int c0 = (lane >> 3) & 1;
        #pragma unroll
        for (int p = 0; p < 2; p++) bOff[p] = 8192u + swz(r + p * 16, c0) * 16u;
    }

    float acc[4][4][4];
    #pragma unroll
    for (int i = 0; i < 4; i++)
        #pragma unroll
        for (int j = 0; j < 4; j++)
            #pragma unroll
            for (int r = 0; r < 4; r++) acc[i][j][r] = 0.f;

    const int iters = K >> 5;           // K >= 256 -> iters >= 8 > STAGES-1

    #pragma unroll
    for (int s = 0; s < STAGES - 1; ++s) {
        unsigned st = smbase + (unsigned)s * 16384u;
        int k0 = s << 5;
        CP16(st + dA0, gA0 + k0); CP16(st + dA1, gA1 + k0);
        CP16(st + dB0, gB0 + k0); CP16(st + dB1, gB1 + k0);
        COMMIT();
    }

    for (int it = 0; it < iters; ++it) {
        WAITG(STAGES - 2);
        __syncthreads();
        {
            int pf = it + STAGES - 1;
            if (pf < iters) {
                unsigned st = smbase + (unsigned)(pf & (STAGES - 1)) * 16384u;
                int k0 = pf << 5;
                CP16(st + dA0, gA0 + k0); CP16(st + dA1, gA1 + k0);
                CP16(st + dB0, gB0 + k0); CP16(st + dB1, gB1 + k0);
            }
            COMMIT();
        }

        const unsigned sb = smbase + (unsigned)(it & (STAGES - 1)) * 16384u;
        #pragma unroll
        for (int ks = 0; ks < 2; ++ks) {
            const unsigned kx = (unsigned)ks * 32u;
            unsigned a[4][4], b[2][4];
            #pragma unroll
            for (int mt = 0; mt < 4; mt++)
                LDMX4(a[mt][0], a[mt][1], a[mt][2], a[mt][3], sb + (aOff[mt] ^ kx));
            #pragma unroll
            for (int p = 0; p < 2; p++)
                LDMX4(b[p][0], b[p][1], b[p][2], b[p][3], sb + (bOff[p] ^ kx));

            #pragma unroll
            for (int mt = 0; mt < 4; mt++) {
                #pragma unroll
                for (int nt = 0; nt < 4; nt++) {
                    const int p = nt >> 1, h = (nt & 1) << 1;
                    MMA16816(acc[mt][nt][0], acc[mt][nt][1], acc[mt][nt][2], acc[mt][nt][3],
                             a[mt][0], a[mt][1], a[mt][2], a[mt][3],
                             b[p][h + 0], b[p][h + 1]);
                }
            }
        }
    }

    // epilogue: c0 @(r,cc) c1 @(r,cc+1) c2 @(r+8,cc) c3 @(r+8,cc+1)
    const int row = m0 + wm * 64 + (lane >> 2);
    const int col = n0 + wn * 32 + (lane & 3) * 2;

    if (EPI == 4) {
        float* D = (float*)Dv + (size_t)bz * sD;
        const float* R = resid + (size_t)bz * sD;
        #pragma unroll
        for (int mt = 0; mt < 4; mt++) {
            #pragma unroll
            for (int nt = 0; nt < 4; nt++) {
                int r = row + mt * 16, cc = col + nt * 8;
                float b0 = bias[r], b1 = bias[r + 8];
                float2 v0 = { acc[mt][nt][0] + b0, acc[mt][nt][1] + b0 };
                float2 v1 = { acc[mt][nt][2] + b1, acc[mt][nt][3] + b1 };
                float2 r0 = *(const float2*)(&R[(size_t)r * N + cc]);
                float2 r1 = *(const float2*)(&R[(size_t)(r + 8) * N + cc]);
                v0.x += r0.x; v0.y += r0.y; v1.x += r1.x; v1.y += r1.y;
                *(float2*)(&D[(size_t)r * N + cc])       = v0;
                *(float2*)(&D[(size_t)(r + 8) * N + cc]) = v1;
            }
        }
    } else if (EPI == 5) {
        // exp epilogue + row-sum atomics (scores). M == HW, rows are i.
        bf16* D = (bf16*)Dv + (size_t)bz * sD;
        float* lrow = lptr + (size_t)bz * M;
        #pragma unroll
        for (int mt = 0; mt < 4; mt++) {
            const int r = row + mt * 16;
            float s0 = 0.f, s1 = 0.f;
            #pragma unroll
            for (int nt = 0; nt < 4; nt++) {
                int cc = col + nt * 8;
                float e0 = __expf(acc[mt][nt][0] * scale);
                float e1 = __expf(acc[mt][nt][1] * scale);
                float e2 = __expf(acc[mt][nt][2] * scale);
                float e3 = __expf(acc[mt][nt][3] * scale);
                s0 += e0 + e1;  s1 += e2 + e3;
                __nv_bfloat162 o0 = __floats2bfloat162_rn(e0, e1);
                __nv_bfloat162 o1 = __floats2bfloat162_rn(e2, e3);
                *(__nv_bfloat162*)(&D[(size_t)r * N + cc])       = o0;
                *(__nv_bfloat162*)(&D[(size_t)(r + 8) * N + cc]) = o1;
            }
            // reduce across the quad (lanes sharing a row), then one atomic per row
            s0 += __shfl_xor_sync(0xffffffffu, s0, 1);
            s0 += __shfl_xor_sync(0xffffffffu, s0, 2);
            s1 += __shfl_xor_sync(0xffffffffu, s1, 1);
            s1 += __shfl_xor_sync(0xffffffffu, s1, 2);
            if ((lane & 3) == 0) {
                atomicAdd(&lrow[r],     s0);
                atomicAdd(&lrow[r + 8], s1);
            }
        }
    } else if (EPI == 6) {
        // divide-by-rowsum epilogue (attn). M == HW, rows are i.
        bf16* D = (bf16*)Dv + (size_t)bz * sD;
        const float* lrow = lptr + (size_t)bz * M;
        #pragma unroll
        for (int mt = 0; mt < 4; mt++) {
            const int r = row + mt * 16;
            const float inv0 = 1.0f / lrow[r];
            const float inv1 = 1.0f / lrow[r + 8];
            #pragma unroll
            for (int nt = 0; nt < 4; nt++) {
                int cc = col + nt * 8;
                __nv_bfloat162 o0 = __floats2bfloat162_rn(acc[mt][nt][0] * inv0,
                                                          acc[mt][nt][1] * inv0);
                __nv_bfloat162 o1 = __floats2bfloat162_rn(acc[mt][nt][2] * inv1,
                                                          acc[mt][nt][3] * inv1);
                *(__nv_bfloat162*)(&D[(size_t)r * N + cc])       = o0;
                *(__nv_bfloat162*)(&D[(size_t)(r + 8) * N + cc]) = o1;
            }
        }
    } else {
        bf16* D = (bf16*)Dv + (size_t)bz * sD;
        #pragma unroll
        for (int mt = 0; mt < 4; mt++) {
            #pragma unroll
            for (int nt = 0; nt < 4; nt++) {
                int r = row + mt * 16, cc = col + nt * 8;
                float bn0 = 0.f, bn1 = 0.f, bm0 = 0.f, bm1 = 0.f;
                if (EPI == 1) { bn0 = bias[cc]; bn1 = bias[cc + 1]; }
                if (EPI == 2) { bm0 = bias[r];  bm1 = bias[r + 8]; }
                __nv_bfloat162 o0, o1;
                o0.x = __float2bfloat16_rn(acc[mt][nt][0] * scale + bn0 + bm0);
                o0.y = __float2bfloat16_rn(acc[mt][nt][1] * scale + bn1 + bm0);
                o1.x = __float2bfloat16_rn(acc[mt][nt][2] * scale + bn0 + bm1);
                o1.y = __float2bfloat16_rn(acc[mt][nt][3] * scale + bn1 + bm1);
                *(__nv_bfloat162*)(&D[(size_t)r * N + cc])       = o0;
                *(__nv_bfloat162*)(&D[(size_t)(r + 8) * N + cc]) = o1;
            }
        }
    }
}

// ---------------- launch --------------------------------------------------------
extern "C" void kernel_launch(void* const* d_in, const int* in_sizes, int n_in,
                              void* d_out, int out_size) {
    const float* x  = (const float*)d_in[0];
    const float* gs = (const float*)d_in[1];
    const float* gb = (const float*)d_in[2];
    const float* wq = (const float*)d_in[3];
    const float* bq = (const float*)d_in[4];
    const float* wk = (const float*)d_in[5];
    const float* bk = (const float*)d_in[6];
    const float* wv = (const float*)d_in[7];
    const float* bv = (const float*)d_in[8];
    const float* wp = (const float*)d_in[9];
    const float* bp = (const float*)d_in[10];
    float* out = (float*)d_out;

    bf16 *p_ofT, *p_q, *p_k, *p_v, *p_atT, *p_s, *p_w16;
    float *p_l;
    cudaGetSymbolAddress((void**)&p_ofT, g_ofT);
    cudaGetSymbolAddress((void**)&p_q,   g_q);
    cudaGetSymbolAddress((void**)&p_k,   g_k);
    cudaGetSymbolAddress((void**)&p_v,   g_v);
    cudaGetSymbolAddress((void**)&p_atT, g_atT);
    cudaGetSymbolAddress((void**)&p_s,   g_s);
    cudaGetSymbolAddress((void**)&p_w16, g_w16);
    cudaGetSymbolAddress((void**)&p_l,   g_l);

    cudaFuncSetAttribute(mma_gemm<1>, cudaFuncAttributeMaxDynamicSharedMemorySize, GEMM_SMEM_BYTES);
    cudaFuncSetAttribute(mma_gemm<2>, cudaFuncAttributeMaxDynamicSharedMemorySize, GEMM_SMEM_BYTES);
    cudaFuncSetAttribute(mma_gemm<4>, cudaFuncAttributeMaxDynamicSharedMemorySize, GEMM_SMEM_BYTES);
    cudaFuncSetAttribute(mma_gemm<5>, cudaFuncAttributeMaxDynamicSharedMemorySize, GEMM_SMEM_BYTES);
    cudaFuncSetAttribute(mma_gemm<6>, cudaFuncAttributeMaxDynamicSharedMemorySize, GEMM_SMEM_BYTES);

    const long long sIC = (long long)HW * CH;   // [i][c] per-batch stride
    const long long sCI = (long long)CH * HW;   // [c][i] per-batch stride
    const long long sW  = (long long)HW * HW;

    // 1) GroupNorm + weight conversion + row-sum zeroing
    gn_stats<<<BATCH * NGROUP, 256>>>(x);
    zero_l<<<BATCH * HW / 256, 256>>>();
    conv_w<<<CH * CH / 256, 256>>>(wq, wk, wv, wp);
    gn_apply_t<<<dim3(HW / 32, CH / 32, BATCH), dim3(32, 8)>>>(x, gs, gb);

    // 2) Q/K: [i][c_out] = OF^T x W^T + bias[n]
    dim3 gQK(CH / 128, HW / 128, BATCH);
    mma_gemm<1><<<gQK, 256, GEMM_SMEM_BYTES>>>(p_ofT, p_w16 + 0 * CH * CH, p_q, HW, CH, CH, sIC, 0, sIC, 1.0f, bq, nullptr);
    mma_gemm<1><<<gQK, 256, GEMM_SMEM_BYTES>>>(p_ofT, p_w16 + 1 * CH * CH, p_k, HW, CH, CH, sIC, 0, sIC, 1.0f, bk, nullptr);
    // V: [c][j] = W x OF + bias[m]
    dim3 gV(HW / 128, CH / 128, BATCH);
    mma_gemm<2><<<gV, 256, GEMM_SMEM_BYTES>>>(p_w16 + 2 * CH * CH, p_ofT, p_v, CH, HW, CH, 0, sIC, sCI, 1.0f, bv, nullptr);

    // 3) scores -> expS (bf16) + row sums l  (softmax without max-subtraction)
    dim3 gS(HW / 128, HW / 128, BATCH);
    mma_gemm<5><<<gS, 256, GEMM_SMEM_BYTES>>>(p_q, p_k, p_s, HW, HW, CH, sIC, sIC, sW, 0.0625f, nullptr, nullptr, p_l);

    // 4) attn (transposed): atT[i][c] = (1/l_i) * sum_j expS[i,j] V[c,j]
    dim3 gA(CH / 128, HW / 128, BATCH);
    mma_gemm<6><<<gA, 256, GEMM_SMEM_BYTES>>>(p_s, p_v, p_atT, HW, CH, HW, sW, sCI, sIC, 1.0f, nullptr, nullptr, p_l);

    // 5) proj + bias + residual -> d_out
    dim3 gP(HW / 128, CH / 128, BATCH);
    mma_gemm<4><<<gP, 256, GEMM_SMEM_BYTES>>>(p_w16 + 3 * CH * CH, p_atT, out, CH, HW, CH, 0, sIC, sCI, 1.0f, bp, x);
}

// round 10
// speedup vs baseline: 1.5171x; 1.5171x over previous
#include <cuda_runtime.h>
#include <cuda_bf16.h>
#include <math.h>
#include <stdint.h>

#define BATCH  4
#define CH     256
#define NGROUP 32
#define HW     4096
#define GEPS   1e-6f
#define STAGES 4

typedef __nv_bfloat16 bf16;

// ---------------- scratch (device globals; no allocation allowed) -------------
__device__ bf16  g_ofT[(size_t)BATCH * HW * CH];   // GN output, transposed [b][i][c]
__device__ bf16  g_q  [(size_t)BATCH * HW * CH];   // Q  [b][i][c]
__device__ bf16  g_k  [(size_t)BATCH * HW * CH];   // K  [b][j][c]
__device__ bf16  g_v  [(size_t)BATCH * CH * HW];   // V  [b][c][j]
__device__ bf16  g_atT[(size_t)BATCH * HW * CH];   // attn out transposed [b][i][c]
__device__ bf16  g_s  [(size_t)BATCH * HW * HW];   // expS bf16 (134MB)
__device__ bf16  g_w16[4 * CH * CH];               // bf16 weights: wq|wk|wv|wp
__device__ float g_l  [BATCH * HW];                // softmax row sums (atomic)
__device__ float g_mean[BATCH * NGROUP];
__device__ float g_rstd[BATCH * NGROUP];

// ---------------- GroupNorm: stats --------------------------------------------
__global__ void __launch_bounds__(256) gn_stats(const float* __restrict__ x) {
    const int bg = blockIdx.x;
    const float* p = x + (size_t)bg * (CH / NGROUP) * HW;
    const int tid = threadIdx.x;

    float s = 0.f, s2 = 0.f;
    const int n4 = (CH / NGROUP) * HW / 4;
    for (int i = tid; i < n4; i += 256) {
        float4 v = ((const float4*)p)[i];
        s  += v.x + v.y + v.z + v.w;
        s2 += v.x * v.x + v.y * v.y + v.z * v.z + v.w * v.w;
    }
    __shared__ float red[64];
    #pragma unroll
    for (int o = 16; o; o >>= 1) {
        s  += __shfl_xor_sync(0xffffffffu, s,  o);
        s2 += __shfl_xor_sync(0xffffffffu, s2, o);
    }
    if ((tid & 31) == 0) { red[tid >> 5] = s; red[32 + (tid >> 5)] = s2; }
    __syncthreads();
    if (tid == 0) {
        float ts = 0.f, ts2 = 0.f;
        #pragma unroll
        for (int w = 0; w < 8; w++) { ts += red[w]; ts2 += red[32 + w]; }
        const float inv_n = 1.0f / ((CH / NGROUP) * HW);
        float mean = ts * inv_n;
        float var  = ts2 * inv_n - mean * mean;
        g_mean[bg] = mean;
        g_rstd[bg] = rsqrtf(var + GEPS);
    }
}

// ---------------- zero the softmax row-sum accumulator --------------------------
__global__ void __launch_bounds__(256) zero_l() {
    g_l[blockIdx.x * 256 + threadIdx.x] = 0.f;
}

// ---------------- GroupNorm apply + transpose -> bf16 OF^T [b][i][c] -----------
__global__ void __launch_bounds__(256) gn_apply_t(const float* __restrict__ x,
                                                  const float* __restrict__ gs,
                                                  const float* __restrict__ gb) {
    __shared__ float tile[32][33];
    const int i0 = blockIdx.x * 32, c0 = blockIdx.y * 32, b = blockIdx.z;
    const int tx = threadIdx.x, ty = threadIdx.y;

    #pragma unroll
    for (int dy = 0; dy < 4; dy++) {
        int c = c0 + ty + dy * 8;
        int bg = b * NGROUP + (c >> 3);
        float r = g_rstd[bg];
        float a = gs[c] * r;
        float t = gb[c] - g_mean[bg] * a;
        float v = x[((size_t)b * CH + c) * HW + i0 + tx];
        tile[ty + dy * 8][tx] = v * a + t;
    }
    __syncthreads();

    const int tid = ty * 32 + tx;
    #pragma unroll
    for (int h = 0; h < 2; h++) {
        int p = tid + h * 256;
        int il = p >> 4, cl = (p & 15) * 2;
        __nv_bfloat162 o;
        o.x = __float2bfloat16_rn(tile[cl][il]);
        o.y = __float2bfloat16_rn(tile[cl + 1][il]);
        *(__nv_bfloat162*)(&g_ofT[((size_t)b * HW + i0 + il) * CH + c0 + cl]) = o;
    }
}

// ---------------- weights -> bf16 ----------------------------------------------
__global__ void __launch_bounds__(256) conv_w(const float* __restrict__ wq,
                                              const float* __restrict__ wk,
                                              const float* __restrict__ wv,
                                              const float* __restrict__ wp) {
    int i = blockIdx.x * 256 + threadIdx.x;
    if (i >= CH * CH) return;
    g_w16[0 * CH * CH + i] = __float2bfloat16_rn(wq[i]);
    g_w16[1 * CH * CH + i] = __float2bfloat16_rn(wk[i]);
    g_w16[2 * CH * CH + i] = __float2bfloat16_rn(wv[i]);
    g_w16[3 * CH * CH + i] = __float2bfloat16_rn(wp[i]);
}

// ---------------- bf16 tensor-core GEMM (mma.sync HMMA, R5 config) --------------
// D[m][n] = scale * sum_k A[m][k]*B[n][k] (+ epilogue)
// A: [M][K] bf16 k-contig, B: [N][K] bf16 k-contig.
// EPI 1: bf16 out*scale + bias[n].  EPI 2: bf16 out*scale + bias[m].
// EPI 4: fp32 out + bias[m] + resid[m][n].
// EPI 5: bf16 out = exp(acc*scale); atomicAdd per-row sums into lptr.
// EPI 6: bf16 out = acc / lptr[row].
// CTA 128x128, BK=32, 8 warps (2m x 4n), warp tile 64x32, 4-stage cp.async.
// __launch_bounds__(256, 2) pins regs <= 128 so ALL epilogue variants keep
// 2 CTAs/SM (R9 regression root cause: EPI5/6 pushed regs past 128 -> 1 CTA/SM).

__device__ __forceinline__ unsigned swz(int m, int c) {  // 16B-chunk index in [128][32]bf16 tile
    return (unsigned)((m << 2) + (c ^ ((m >> 1) & 3)));
}

#define CP16(dst_u32, src_ptr) \
    asm volatile("cp.async.cg.shared.global [%0], [%1], 16;\n" :: "r"(dst_u32), "l"(src_ptr))
#define LDMX4(r0, r1, r2, r3, addr) \
    asm volatile("ldmatrix.sync.aligned.m8n8.x4.shared.b16 {%0,%1,%2,%3}, [%4];\n" \
                 : "=r"(r0), "=r"(r1), "=r"(r2), "=r"(r3) : "r"(addr))
#define MMA16816(c0, c1, c2, c3, a0, a1, a2, a3, b0, b1) \
    asm volatile("mma.sync.aligned.m16n8k16.row.col.f32.bf16.bf16.f32 " \
                 "{%0,%1,%2,%3}, {%4,%5,%6,%7}, {%8,%9}, {%0,%1,%2,%3};\n" \
                 : "+f"(c0), "+f"(c1), "+f"(c2), "+f"(c3) \
                 : "r"(a0), "r"(a1), "r"(a2), "r"(a3), "r"(b0), "r"(b1))
#define COMMIT() asm volatile("cp.async.commit_group;\n")
#define WAITG(n) asm volatile("cp.async.wait_group %0;\n" :: "n"(n))

#define GEMM_SMEM_BYTES (STAGES * 16384)

template<int EPI>
__global__ void __launch_bounds__(256, 2) mma_gemm(
    const bf16* __restrict__ A, const bf16* __restrict__ B,
    void* __restrict__ Dv, int M, int N, int K,
    long long sA, long long sB, long long sD, float scale,
    const float* __restrict__ bias, const float* __restrict__ resid,
    float* __restrict__ lptr = nullptr)
{
    extern __shared__ __align__(16) unsigned char sm[];   // STAGES x [A 8KB | B 8KB]
    const int bz = blockIdx.z;
    A += (size_t)bz * sA;
    B += (size_t)bz * sB;
    const int m0 = blockIdx.y * 128, n0 = blockIdx.x * 128;
    const int tid = threadIdx.x, lane = tid & 31, warp = tid >> 5;
    const int wm = warp >> 2, wn = warp & 3;

    const unsigned smbase = (unsigned)__cvta_generic_to_shared(sm);

    const int lm = tid >> 2, lc = tid & 3;
    const bf16* gA0 = A + (size_t)(m0 + lm)      * K + lc * 8;
    const bf16* gA1 = A + (size_t)(m0 + lm + 64) * K + lc * 8;
    const bf16* gB0 = B + (size_t)(n0 + lm)      * K + lc * 8;
    const bf16* gB1 = B + (size_t)(n0 + lm + 64) * K + lc * 8;
    const unsigned dA0 = swz(lm, lc) * 16u;
    const unsigned dA1 = swz(lm + 64, lc) * 16u;
    const unsigned dB0 = 8192u + swz(lm, lc) * 16u;
    const unsigned dB1 = 8192u + swz(lm + 64, lc) * 16u;

    unsigned aOff[4], bOff[2];
    {
        int r = wm * 64 + (lane & 15);
        int c0 = lane >> 4;
        #pragma unroll
        for (int mt = 0; mt < 4; mt++) aOff[mt] = swz(r + mt * 16, c0) * 16u;
    }
    {
        int r = wn * 32 + ((lane >> 4) << 3) + (lane & 7);
        int c0 = (lane >> 3) & 1;
        #pragma unroll
        for (int p = 0; p < 2; p++) bOff[p] = 8192u + swz(r + p * 16, c0) * 16u;
    }

    float acc[4][4][4];
    #pragma unroll
    for (int i = 0; i < 4; i++)
        #pragma unroll
        for (int j = 0; j < 4; j++)
            #pragma unroll
            for (int r = 0; r < 4; r++) acc[i][j][r] = 0.f;

    const int iters = K >> 5;           // K >= 256 -> iters >= 8 > STAGES-1

    #pragma unroll
    for (int s = 0; s < STAGES - 1; ++s) {
        unsigned st = smbase + (unsigned)s * 16384u;
        int k0 = s << 5;
        CP16(st + dA0, gA0 + k0); CP16(st + dA1, gA1 + k0);
        CP16(st + dB0, gB0 + k0); CP16(st + dB1, gB1 + k0);
        COMMIT();
    }

    for (int it = 0; it < iters; ++it) {
        WAITG(STAGES - 2);
        __syncthreads();
        {
            int pf = it + STAGES - 1;
            if (pf < iters) {
                unsigned st = smbase + (unsigned)(pf & (STAGES - 1)) * 16384u;
                int k0 = pf << 5;
                CP16(st + dA0, gA0 + k0); CP16(st + dA1, gA1 + k0);
                CP16(st + dB0, gB0 + k0); CP16(st + dB1, gB1 + k0);
            }
            COMMIT();
        }

        const unsigned sb = smbase + (unsigned)(it & (STAGES - 1)) * 16384u;
        #pragma unroll
        for (int ks = 0; ks < 2; ++ks) {
            const unsigned kx = (unsigned)ks * 32u;
            unsigned a[4][4], b[2][4];
            #pragma unroll
            for (int mt = 0; mt < 4; mt++)
                LDMX4(a[mt][0], a[mt][1], a[mt][2], a[mt][3], sb + (aOff[mt] ^ kx));
            #pragma unroll
            for (int p = 0; p < 2; p++)
                LDMX4(b[p][0], b[p][1], b[p][2], b[p][3], sb + (bOff[p] ^ kx));

            #pragma unroll
            for (int mt = 0; mt < 4; mt++) {
                #pragma unroll
                for (int nt = 0; nt < 4; nt++) {
                    const int p = nt >> 1, h = (nt & 1) << 1;
                    MMA16816(acc[mt][nt][0], acc[mt][nt][1], acc[mt][nt][2], acc[mt][nt][3],
                             a[mt][0], a[mt][1], a[mt][2], a[mt][3],
                             b[p][h + 0], b[p][h + 1]);
                }
            }
        }
    }

    // epilogue: c0 @(r,cc) c1 @(r,cc+1) c2 @(r+8,cc) c3 @(r+8,cc+1)
    const int row = m0 + wm * 64 + (lane >> 2);
    const int col = n0 + wn * 32 + (lane & 3) * 2;

    if (EPI == 4) {
        float* D = (float*)Dv + (size_t)bz * sD;
        const float* R = resid + (size_t)bz * sD;
        #pragma unroll
        for (int mt = 0; mt < 4; mt++) {
            #pragma unroll
            for (int nt = 0; nt < 4; nt++) {
                int r = row + mt * 16, cc = col + nt * 8;
                float b0 = bias[r], b1 = bias[r + 8];
                float2 v0 = { acc[mt][nt][0] + b0, acc[mt][nt][1] + b0 };
                float2 v1 = { acc[mt][nt][2] + b1, acc[mt][nt][3] + b1 };
                float2 r0 = *(const float2*)(&R[(size_t)r * N + cc]);
                float2 r1 = *(const float2*)(&R[(size_t)(r + 8) * N + cc]);
                v0.x += r0.x; v0.y += r0.y; v1.x += r1.x; v1.y += r1.y;
                *(float2*)(&D[(size_t)r * N + cc])       = v0;
                *(float2*)(&D[(size_t)(r + 8) * N + cc]) = v1;
            }
        }
    } else if (EPI == 5) {
        // exp epilogue + row-sum atomics (scores). M == HW, rows are i.
        bf16* D = (bf16*)Dv + (size_t)bz * sD;
        float* lrow = lptr + (size_t)bz * M;
        #pragma unroll
        for (int mt = 0; mt < 4; mt++) {
            const int r = row + mt * 16;
            float s0 = 0.f, s1 = 0.f;
            #pragma unroll
            for (int nt = 0; nt < 4; nt++) {
                int cc = col + nt * 8;
                float e0 = __expf(acc[mt][nt][0] * scale);
                float e1 = __expf(acc[mt][nt][1] * scale);
                float e2 = __expf(acc[mt][nt][2] * scale);
                float e3 = __expf(acc[mt][nt][3] * scale);
                s0 += e0 + e1;  s1 += e2 + e3;
                __nv_bfloat162 o0 = __floats2bfloat162_rn(e0, e1);
                __nv_bfloat162 o1 = __floats2bfloat162_rn(e2, e3);
                *(__nv_bfloat162*)(&D[(size_t)r * N + cc])       = o0;
                *(__nv_bfloat162*)(&D[(size_t)(r + 8) * N + cc]) = o1;
            }
            // reduce across the quad (lanes sharing a row), then one atomic per row
            s0 += __shfl_xor_sync(0xffffffffu, s0, 1);
            s0 += __shfl_xor_sync(0xffffffffu, s0, 2);
            s1 += __shfl_xor_sync(0xffffffffu, s1, 1);
            s1 += __shfl_xor_sync(0xffffffffu, s1, 2);
            if ((lane & 3) == 0) {
                atomicAdd(&lrow[r],     s0);
                atomicAdd(&lrow[r + 8], s1);
            }
        }
    } else if (EPI == 6) {
        // divide-by-rowsum epilogue (attn). M == HW, rows are i.
        bf16* D = (bf16*)Dv + (size_t)bz * sD;
        const float* lrow = lptr + (size_t)bz * M;
        #pragma unroll
        for (int mt = 0; mt < 4; mt++) {
            const int r = row + mt * 16;
            const float inv0 = 1.0f / lrow[r];
            const float inv1 = 1.0f / lrow[r + 8];
            #pragma unroll
            for (int nt = 0; nt < 4; nt++) {
                int cc = col + nt * 8;
                __nv_bfloat162 o0 = __floats2bfloat162_rn(acc[mt][nt][0] * inv0,
                                                          acc[mt][nt][1] * inv0);
                __nv_bfloat162 o1 = __floats2bfloat162_rn(acc[mt][nt][2] * inv1,
                                                          acc[mt][nt][3] * inv1);
                *(__nv_bfloat162*)(&D[(size_t)r * N + cc])       = o0;
                *(__nv_bfloat162*)(&D[(size_t)(r + 8) * N + cc]) = o1;
            }
        }
    } else {
        bf16* D = (bf16*)Dv + (size_t)bz * sD;
        #pragma unroll
        for (int mt = 0; mt < 4; mt++) {
            #pragma unroll
            for (int nt = 0; nt < 4; nt++) {
                int r = row + mt * 16, cc = col + nt * 8;
                float bn0 = 0.f, bn1 = 0.f, bm0 = 0.f, bm1 = 0.f;
                if (EPI == 1) { bn0 = bias[cc]; bn1 = bias[cc + 1]; }
                if (EPI == 2) { bm0 = bias[r];  bm1 = bias[r + 8]; }
                __nv_bfloat162 o0, o1;
                o0.x = __float2bfloat16_rn(acc[mt][nt][0] * scale + bn0 + bm0);
                o0.y = __float2bfloat16_rn(acc[mt][nt][1] * scale + bn1 + bm0);
                o1.x = __float2bfloat16_rn(acc[mt][nt][2] * scale + bn0 + bm1);
                o1.y = __float2bfloat16_rn(acc[mt][nt][3] * scale + bn1 + bm1);
                *(__nv_bfloat162*)(&D[(size_t)r * N + cc])       = o0;
                *(__nv_bfloat162*)(&D[(size_t)(r + 8) * N + cc]) = o1;
            }
        }
    }
}

// ---------------- launch --------------------------------------------------------
extern "C" void kernel_launch(void* const* d_in, const int* in_sizes, int n_in,
                              void* d_out, int out_size) {
    const float* x  = (const float*)d_in[0];
    const float* gs = (const float*)d_in[1];
    const float* gb = (const float*)d_in[2];
    const float* wq = (const float*)d_in[3];
    const float* bq = (const float*)d_in[4];
    const float* wk = (const float*)d_in[5];
    const float* bk = (const float*)d_in[6];
    const float* wv = (const float*)d_in[7];
    const float* bv = (const float*)d_in[8];
    const float* wp = (const float*)d_in[9];
    const float* bp = (const float*)d_in[10];
    float* out = (float*)d_out;

    bf16 *p_ofT, *p_q, *p_k, *p_v, *p_atT, *p_s, *p_w16;
    float *p_l;
    cudaGetSymbolAddress((void**)&p_ofT, g_ofT);
    cudaGetSymbolAddress((void**)&p_q,   g_q);
    cudaGetSymbolAddress((void**)&p_k,   g_k);
    cudaGetSymbolAddress((void**)&p_v,   g_v);
    cudaGetSymbolAddress((void**)&p_atT, g_atT);
    cudaGetSymbolAddress((void**)&p_s,   g_s);
    cudaGetSymbolAddress((void**)&p_w16, g_w16);
    cudaGetSymbolAddress((void**)&p_l,   g_l);

    cudaFuncSetAttribute(mma_gemm<1>, cudaFuncAttributeMaxDynamicSharedMemorySize, GEMM_SMEM_BYTES);
    cudaFuncSetAttribute(mma_gemm<2>, cudaFuncAttributeMaxDynamicSharedMemorySize, GEMM_SMEM_BYTES);
    cudaFuncSetAttribute(mma_gemm<4>, cudaFuncAttributeMaxDynamicSharedMemorySize, GEMM_SMEM_BYTES);
    cudaFuncSetAttribute(mma_gemm<5>, cudaFuncAttributeMaxDynamicSharedMemorySize, GEMM_SMEM_BYTES);
    cudaFuncSetAttribute(mma_gemm<6>, cudaFuncAttributeMaxDynamicSharedMemorySize, GEMM_SMEM_BYTES);

    const long long sIC = (long long)HW * CH;   // [i][c] per-batch stride
    const long long sCI = (long long)CH * HW;   // [c][i] per-batch stride
    const long long sW  = (long long)HW * HW;

    // 1) GroupNorm + weight conversion + row-sum zeroing
    gn_stats<<<BATCH * NGROUP, 256>>>(x);
    zero_l<<<BATCH * HW / 256, 256>>>();
    conv_w<<<CH * CH / 256, 256>>>(wq, wk, wv, wp);
    gn_apply_t<<<dim3(HW / 32, CH / 32, BATCH), dim3(32, 8)>>>(x, gs, gb);

    // 2) Q/K: [i][c_out] = OF^T x W^T + bias[n]
    dim3 gQK(CH / 128, HW / 128, BATCH);
    mma_gemm<1><<<gQK, 256, GEMM_SMEM_BYTES>>>(p_ofT, p_w16 + 0 * CH * CH, p_q, HW, CH, CH, sIC, 0, sIC, 1.0f, bq, nullptr);
    mma_gemm<1><<<gQK, 256, GEMM_SMEM_BYTES>>>(p_ofT, p_w16 + 1 * CH * CH, p_k, HW, CH, CH, sIC, 0, sIC, 1.0f, bk, nullptr);
    // V: [c][j] = W x OF + bias[m]
    dim3 gV(HW / 128, CH / 128, BATCH);
    mma_gemm<2><<<gV, 256, GEMM_SMEM_BYTES>>>(p_w16 + 2 * CH * CH, p_ofT, p_v, CH, HW, CH, 0, sIC, sCI, 1.0f, bv, nullptr);

    // 3) scores -> expS (bf16) + row sums l  (softmax without max-subtraction)
    dim3 gS(HW / 128, HW / 128, BATCH);
    mma_gemm<5><<<gS, 256, GEMM_SMEM_BYTES>>>(p_q, p_k, p_s, HW, HW, CH, sIC, sIC, sW, 0.0625f, nullptr, nullptr, p_l);

    // 4) attn (transposed): atT[i][c] = (1/l_i) * sum_j expS[i,j] V[c,j]
    dim3 gA(CH / 128, HW / 128, BATCH);
    mma_gemm<6><<<gA, 256, GEMM_SMEM_BYTES>>>(p_s, p_v, p_atT, HW, CH, HW, sW, sCI, sIC, 1.0f, nullptr, nullptr, p_l);

    // 5) proj + bias + residual -> d_out
    dim3 gP(HW / 128, CH / 128, BATCH);
    mma_gemm<4><<<gP, 256, GEMM_SMEM_BYTES>>>(p_w16 + 3 * CH * CH, p_atT, out, CH, HW, CH, 0, sIC, sCI, 1.0f, bp, x);
}

// round 11
// speedup vs baseline: 1.5331x; 1.0105x over previous
#include <cuda_runtime.h>
#include <cuda_bf16.h>
#include <math.h>
#include <stdint.h>

#define BATCH  4
#define CH     256
#define NGROUP 32
#define HW     4096
#define GEPS   1e-6f
#define STAGES 4

typedef __nv_bfloat16 bf16;

// ---------------- scratch (device globals; no allocation allowed) -------------
__device__ bf16  g_ofT[(size_t)BATCH * HW * CH];   // GN output, transposed [b][i][c]
__device__ bf16  g_q  [(size_t)BATCH * HW * CH];   // Q  [b][i][c]
__device__ bf16  g_k  [(size_t)BATCH * HW * CH];   // K  [b][j][c]
__device__ bf16  g_v  [(size_t)BATCH * CH * HW];   // V  [b][c][j]
__device__ bf16  g_atT[(size_t)BATCH * HW * CH];   // attn out transposed [b][i][c]
__device__ bf16  g_s  [(size_t)BATCH * HW * HW];   // expS bf16 (134MB)
__device__ bf16  g_w16[4 * CH * CH];               // bf16 weights: wq|wk|wv|wp
__device__ float g_l  [BATCH * HW];                // softmax row sums (atomic)
__device__ float g_mean[BATCH * NGROUP];
__device__ float g_rstd[BATCH * NGROUP];

// ---------------- GroupNorm: stats (+ zero g_l slice) ---------------------------
__global__ void __launch_bounds__(256) gn_stats(const float* __restrict__ x) {
    const int bg = blockIdx.x;                       // 0..127
    const float* p = x + (size_t)bg * (CH / NGROUP) * HW;
    const int tid = threadIdx.x;

    if (tid < 128) g_l[bg * 128 + tid] = 0.f;        // fused zero_l (BATCH*HW = 128*128)

    float s = 0.f, s2 = 0.f;
    const int n4 = (CH / NGROUP) * HW / 4;
    for (int i = tid; i < n4; i += 256) {
        float4 v = ((const float4*)p)[i];
        s  += v.x + v.y + v.z + v.w;
        s2 += v.x * v.x + v.y * v.y + v.z * v.z + v.w * v.w;
    }
    __shared__ float red[64];
    #pragma unroll
    for (int o = 16; o; o >>= 1) {
        s  += __shfl_xor_sync(0xffffffffu, s,  o);
        s2 += __shfl_xor_sync(0xffffffffu, s2, o);
    }
    if ((tid & 31) == 0) { red[tid >> 5] = s; red[32 + (tid >> 5)] = s2; }
    __syncthreads();
    if (tid == 0) {
        float ts = 0.f, ts2 = 0.f;
        #pragma unroll
        for (int w = 0; w < 8; w++) { ts += red[w]; ts2 += red[32 + w]; }
        const float inv_n = 1.0f / ((CH / NGROUP) * HW);
        float mean = ts * inv_n;
        float var  = ts2 * inv_n - mean * mean;
        g_mean[bg] = mean;
        g_rstd[bg] = rsqrtf(var + GEPS);
    }
}

// ---------------- GroupNorm apply + transpose -> bf16 OF^T [b][i][c] -----------
// 32i x 64c tiles; loads and stores both fully 128B-coalesced.
__global__ void __launch_bounds__(256) gn_apply_t(const float* __restrict__ x,
                                                  const float* __restrict__ gs,
                                                  const float* __restrict__ gb) {
    __shared__ float tile[64][33];                   // [c_local][i_local]
    const int i0 = blockIdx.x * 32, c0 = blockIdx.y * 64, b = blockIdx.z;
    const int tid = threadIdx.x;
    const int il = tid & 31, cbase = tid >> 5;       // 8 c-rows per pass

    #pragma unroll
    for (int cc = 0; cc < 8; cc++) {
        int cl = cbase + cc * 8;                     // 0..63
        int c = c0 + cl;
        int bg = b * NGROUP + (c >> 3);              // 8 channels per group
        float r = g_rstd[bg];
        float a = gs[c] * r;
        float t = gb[c] - g_mean[bg] * a;
        float v = x[((size_t)b * CH + c) * HW + i0 + il];
        tile[cl][il] = v * a + t;
    }
    __syncthreads();

    #pragma unroll
    for (int h = 0; h < 4; h++) {
        int p = tid + h * 256;                       // 1024 bf162 slots
        int ir = p >> 5, cl = (p & 31) * 2;          // row 0..31, col 0..62
        __nv_bfloat162 o;
        o.x = __float2bfloat16_rn(tile[cl][ir]);
        o.y = __float2bfloat16_rn(tile[cl + 1][ir]);
        *(__nv_bfloat162*)(&g_ofT[((size_t)b * HW + i0 + ir) * CH + c0 + cl]) = o;
    }
}

// ---------------- weights -> bf16 ----------------------------------------------
__global__ void __launch_bounds__(256) conv_w(const float* __restrict__ wq,
                                              const float* __restrict__ wk,
                                              const float* __restrict__ wv,
                                              const float* __restrict__ wp) {
    int i = blockIdx.x * 256 + threadIdx.x;
    if (i >= CH * CH) return;
    g_w16[0 * CH * CH + i] = __float2bfloat16_rn(wq[i]);
    g_w16[1 * CH * CH + i] = __float2bfloat16_rn(wk[i]);
    g_w16[2 * CH * CH + i] = __float2bfloat16_rn(wv[i]);
    g_w16[3 * CH * CH + i] = __float2bfloat16_rn(wp[i]);
}

// ---------------- bf16 tensor-core GEMM (mma.sync HMMA, R5 config) --------------
// D[m][n] = scale * sum_k A[m][k]*B[n][k] (+ epilogue)
// A: [M][K] bf16 k-contig, B: [N][K] bf16 k-contig.
// EPI 2: bf16 out*scale + bias[m].
// EPI 4: fp32 out + bias[m] + resid[m][n].
// EPI 5: bf16 out = exp(acc*scale); atomicAdd per-row sums into lptr.
// EPI 6: bf16 out = acc / lptr[row].
// EPI 7: fused Q|K projection: grid.x=4; x>>1 selects {Dv,bias} vs {Dv2,bias2};
//        B rows addressed over the concatenated 512-row weight; bias[n] epilogue.
// CTA 128x128, BK=32, 8 warps (2m x 4n), warp tile 64x32, 4-stage cp.async.
// __launch_bounds__(256, 2) pins regs <= 128 so all epilogue variants keep 2 CTAs/SM.

__device__ __forceinline__ unsigned swz(int m, int c) {  // 16B-chunk index in [128][32]bf16 tile
    return (unsigned)((m << 2) + (c ^ ((m >> 1) & 3)));
}

#define CP16(dst_u32, src_ptr) \
    asm volatile("cp.async.cg.shared.global [%0], [%1], 16;\n" :: "r"(dst_u32), "l"(src_ptr))
#define LDMX4(r0, r1, r2, r3, addr) \
    asm volatile("ldmatrix.sync.aligned.m8n8.x4.shared.b16 {%0,%1,%2,%3}, [%4];\n" \
                 : "=r"(r0), "=r"(r1), "=r"(r2), "=r"(r3) : "r"(addr))
#define MMA16816(c0, c1, c2, c3, a0, a1, a2, a3, b0, b1) \
    asm volatile("mma.sync.aligned.m16n8k16.row.col.f32.bf16.bf16.f32 " \
                 "{%0,%1,%2,%3}, {%4,%5,%6,%7}, {%8,%9}, {%0,%1,%2,%3};\n" \
                 : "+f"(c0), "+f"(c1), "+f"(c2), "+f"(c3) \
                 : "r"(a0), "r"(a1), "r"(a2), "r"(a3), "r"(b0), "r"(b1))
#define COMMIT() asm volatile("cp.async.commit_group;\n")
#define WAITG(n) asm volatile("cp.async.wait_group %0;\n" :: "n"(n))

#define GEMM_SMEM_BYTES (STAGES * 16384)

template<int EPI>
__global__ void __launch_bounds__(256, 2) mma_gemm(
    const bf16* __restrict__ A, const bf16* __restrict__ B,
    void* __restrict__ Dv, int M, int N, int K,
    long long sA, long long sB, long long sD, float scale,
    const float* __restrict__ bias, const float* __restrict__ resid,
    float* __restrict__ lptr = nullptr,
    void* __restrict__ Dv2 = nullptr, const float* __restrict__ bias2 = nullptr)
{
    extern __shared__ __align__(16) unsigned char sm[];   // STAGES x [A 8KB | B 8KB]
    const int bz = blockIdx.z;
    A += (size_t)bz * sA;
    B += (size_t)bz * sB;
    const int m0 = blockIdx.y * 128;
    int n0;                                               // output column base
    if (EPI == 7) {
        B += (size_t)(blockIdx.x * 128) * K;              // rows into concatenated wq|wk
        if (blockIdx.x >> 1) { Dv = Dv2; bias = bias2; }
        n0 = (blockIdx.x & 1) * 128;
    } else {
        n0 = blockIdx.x * 128;
        B += (size_t)n0 * K;
    }
    const int tid = threadIdx.x, lane = tid & 31, warp = tid >> 5;
    const int wm = warp >> 2, wn = warp & 3;

    const unsigned smbase = (unsigned)__cvta_generic_to_shared(sm);

    const int lm = tid >> 2, lc = tid & 3;
    const bf16* gA0 = A + (size_t)(m0 + lm)      * K + lc * 8;
    const bf16* gA1 = A + (size_t)(m0 + lm + 64) * K + lc * 8;
    const bf16* gB0 = B + (size_t)(lm)      * K + lc * 8;
    const bf16* gB1 = B + (size_t)(lm + 64) * K + lc * 8;
    const unsigned dA0 = swz(lm, lc) * 16u;
    const unsigned dA1 = swz(lm + 64, lc) * 16u;
    const unsigned dB0 = 8192u + swz(lm, lc) * 16u;
    const unsigned dB1 = 8192u + swz(lm + 64, lc) * 16u;

    unsigned aOff[4], bOff[2];
    {
        int r = wm * 64 + (lane & 15);
        int c0 = lane >> 4;
        #pragma unroll
        for (int mt = 0; mt < 4; mt++) aOff[mt] = swz(r + mt * 16, c0) * 16u;
    }
    {
        int r = wn * 32 + ((lane >> 4) << 3) + (lane & 7);
        int c0 = (lane >> 3) & 1;
        #pragma unroll
        for (int p = 0; p < 2; p++) bOff[p] = 8192u + swz(r + p * 16, c0) * 16u;
    }

    float acc[4][4][4];
    #pragma unroll
    for (int i = 0; i < 4; i++)
        #pragma unroll
        for (int j = 0; j < 4; j++)
            #pragma unroll
            for (int r = 0; r < 4; r++) acc[i][j][r] = 0.f;

    const int iters = K >> 5;           // K >= 256 -> iters >= 8 > STAGES-1

    #pragma unroll
    for (int s = 0; s < STAGES - 1; ++s) {
        unsigned st = smbase + (unsigned)s * 16384u;
        int k0 = s << 5;
        CP16(st + dA0, gA0 + k0); CP16(st + dA1, gA1 + k0);
        CP16(st + dB0, gB0 + k0); CP16(st + dB1, gB1 + k0);
        COMMIT();
    }

    for (int it = 0; it < iters; ++it) {
        WAITG(STAGES - 2);
        __syncthreads();
        {
            int pf = it + STAGES - 1;
            if (pf < iters) {
                unsigned st = smbase + (unsigned)(pf & (STAGES - 1)) * 16384u;
                int k0 = pf << 5;
                CP16(st + dA0, gA0 + k0); CP16(st + dA1, gA1 + k0);
                CP16(st + dB0, gB0 + k0); CP16(st + dB1, gB1 + k0);
            }
            COMMIT();
        }

        const unsigned sb = smbase + (unsigned)(it & (STAGES - 1)) * 16384u;
        #pragma unroll
        for (int ks = 0; ks < 2; ++ks) {
            const unsigned kx = (unsigned)ks * 32u;
            unsigned a[4][4], b[2][4];
            #pragma unroll
            for (int mt = 0; mt < 4; mt++)
                LDMX4(a[mt][0], a[mt][1], a[mt][2], a[mt][3], sb + (aOff[mt] ^ kx));
            #pragma unroll
            for (int p = 0; p < 2; p++)
                LDMX4(b[p][0], b[p][1], b[p][2], b[p][3], sb + (bOff[p] ^ kx));

            #pragma unroll
            for (int mt = 0; mt < 4; mt++) {
                #pragma unroll
                for (int nt = 0; nt < 4; nt++) {
                    const int p = nt >> 1, h = (nt & 1) << 1;
                    MMA16816(acc[mt][nt][0], acc[mt][nt][1], acc[mt][nt][2], acc[mt][nt][3],
                             a[mt][0], a[mt][1], a[mt][2], a[mt][3],
                             b[p][h + 0], b[p][h + 1]);
                }
            }
        }
    }

    // epilogue: c0 @(r,cc) c1 @(r,cc+1) c2 @(r+8,cc) c3 @(r+8,cc+1)
    const int row = m0 + wm * 64 + (lane >> 2);
    const int col = n0 + wn * 32 + (lane & 3) * 2;

    if (EPI == 4) {
        float* D = (float*)Dv + (size_t)bz * sD;
        const float* R = resid + (size_t)bz * sD;
        #pragma unroll
        for (int mt = 0; mt < 4; mt++) {
            #pragma unroll
            for (int nt = 0; nt < 4; nt++) {
                int r = row + mt * 16, cc = col + nt * 8;
                float b0 = bias[r], b1 = bias[r + 8];
                float2 v0 = { acc[mt][nt][0] + b0, acc[mt][nt][1] + b0 };
                float2 v1 = { acc[mt][nt][2] + b1, acc[mt][nt][3] + b1 };
                float2 r0 = *(const float2*)(&R[(size_t)r * N + cc]);
                float2 r1 = *(const float2*)(&R[(size_t)(r + 8) * N + cc]);
                v0.x += r0.x; v0.y += r0.y; v1.x += r1.x; v1.y += r1.y;
                *(float2*)(&D[(size_t)r * N + cc])       = v0;
                *(float2*)(&D[(size_t)(r + 8) * N + cc]) = v1;
            }
        }
    } else if (EPI == 5) {
        // exp epilogue + row-sum atomics (scores). M == HW, rows are i.
        bf16* D = (bf16*)Dv + (size_t)bz * sD;
        float* lrow = lptr + (size_t)bz * M;
        #pragma unroll
        for (int mt = 0; mt < 4; mt++) {
            const int r = row + mt * 16;
            float s0 = 0.f, s1 = 0.f;
            #pragma unroll
            for (int nt = 0; nt < 4; nt++) {
                int cc = col + nt * 8;
                float e0 = __expf(acc[mt][nt][0] * scale);
                float e1 = __expf(acc[mt][nt][1] * scale);
                float e2 = __expf(acc[mt][nt][2] * scale);
                float e3 = __expf(acc[mt][nt][3] * scale);
                s0 += e0 + e1;  s1 += e2 + e3;
                __nv_bfloat162 o0 = __floats2bfloat162_rn(e0, e1);
                __nv_bfloat162 o1 = __floats2bfloat162_rn(e2, e3);
                *(__nv_bfloat162*)(&D[(size_t)r * N + cc])       = o0;
                *(__nv_bfloat162*)(&D[(size_t)(r + 8) * N + cc]) = o1;
            }
            s0 += __shfl_xor_sync(0xffffffffu, s0, 1);
            s0 += __shfl_xor_sync(0xffffffffu, s0, 2);
            s1 += __shfl_xor_sync(0xffffffffu, s1, 1);
            s1 += __shfl_xor_sync(0xffffffffu, s1, 2);
            if ((lane & 3) == 0) {
                atomicAdd(&lrow[r],     s0);
                atomicAdd(&lrow[r + 8], s1);
            }
        }
    } else if (EPI == 6) {
        // divide-by-rowsum epilogue (attn). M == HW, rows are i.
        bf16* D = (bf16*)Dv + (size_t)bz * sD;
        const float* lrow = lptr + (size_t)bz * M;
        #pragma unroll
        for (int mt = 0; mt < 4; mt++) {
            const int r = row + mt * 16;
            const float inv0 = 1.0f / lrow[r];
            const float inv1 = 1.0f / lrow[r + 8];
            #pragma unroll
            for (int nt = 0; nt < 4; nt++) {
                int cc = col + nt * 8;
                __nv_bfloat162 o0 = __floats2bfloat162_rn(acc[mt][nt][0] * inv0,
                                                          acc[mt][nt][1] * inv0);
                __nv_bfloat162 o1 = __floats2bfloat162_rn(acc[mt][nt][2] * inv1,
                                                          acc[mt][nt][3] * inv1);
                *(__nv_bfloat162*)(&D[(size_t)r * N + cc])       = o0;
                *(__nv_bfloat162*)(&D[(size_t)(r + 8) * N + cc]) = o1;
            }
        }
    } else {
        // EPI 2 (bias[m]) and EPI 7 (bias[n])
        bf16* D = (bf16*)Dv + (size_t)bz * sD;
        #pragma unroll
        for (int mt = 0; mt < 4; mt++) {
            #pragma unroll
            for (int nt = 0; nt < 4; nt++) {
                int r = row + mt * 16, cc = col + nt * 8;
                float bn0 = 0.f, bn1 = 0.f, bm0 = 0.f, bm1 = 0.f;
                if (EPI == 7) { bn0 = bias[cc]; bn1 = bias[cc + 1]; }
                if (EPI == 2) { bm0 = bias[r];  bm1 = bias[r + 8]; }
                __nv_bfloat162 o0, o1;
                o0.x = __float2bfloat16_rn(acc[mt][nt][0] * scale + bn0 + bm0);
                o0.y = __float2bfloat16_rn(acc[mt][nt][1] * scale + bn1 + bm0);
                o1.x = __float2bfloat16_rn(acc[mt][nt][2] * scale + bn0 + bm1);
                o1.y = __float2bfloat16_rn(acc[mt][nt][3] * scale + bn1 + bm1);
                *(__nv_bfloat162*)(&D[(size_t)r * N + cc])       = o0;
                *(__nv_bfloat162*)(&D[(size_t)(r + 8) * N + cc]) = o1;
            }
        }
    }
}

// ---------------- launch --------------------------------------------------------
extern "C" void kernel_launch(void* const* d_in, const int* in_sizes, int n_in,
                              void* d_out, int out_size) {
    const float* x  = (const float*)d_in[0];
    const float* gs = (const float*)d_in[1];
    const float* gb = (const float*)d_in[2];
    const float* wq = (const float*)d_in[3];
    const float* bq = (const float*)d_in[4];
    const float* wk = (const float*)d_in[5];
    const float* bk = (const float*)d_in[6];
    const float* wv = (const float*)d_in[7];
    const float* bv = (const float*)d_in[8];
    const float* wp = (const float*)d_in[9];
    const float* bp = (const float*)d_in[10];
    float* out = (float*)d_out;

    bf16 *p_ofT, *p_q, *p_k, *p_v, *p_atT, *p_s, *p_w16;
    float *p_l;
    cudaGetSymbolAddress((void**)&p_ofT, g_ofT);
    cudaGetSymbolAddress((void**)&p_q,   g_q);
    cudaGetSymbolAddress((void**)&p_k,   g_k);
    cudaGetSymbolAddress((void**)&p_v,   g_v);
    cudaGetSymbolAddress((void**)&p_atT, g_atT);
    cudaGetSymbolAddress((void**)&p_s,   g_s);
    cudaGetSymbolAddress((void**)&p_w16, g_w16);
    cudaGetSymbolAddress((void**)&p_l,   g_l);

    cudaFuncSetAttribute(mma_gemm<2>, cudaFuncAttributeMaxDynamicSharedMemorySize, GEMM_SMEM_BYTES);
    cudaFuncSetAttribute(mma_gemm<4>, cudaFuncAttributeMaxDynamicSharedMemorySize, GEMM_SMEM_BYTES);
    cudaFuncSetAttribute(mma_gemm<5>, cudaFuncAttributeMaxDynamicSharedMemorySize, GEMM_SMEM_BYTES);
    cudaFuncSetAttribute(mma_gemm<6>, cudaFuncAttributeMaxDynamicSharedMemorySize, GEMM_SMEM_BYTES);
    cudaFuncSetAttribute(mma_gemm<7>, cudaFuncAttributeMaxDynamicSharedMemorySize, GEMM_SMEM_BYTES);

    const long long sIC = (long long)HW * CH;   // [i][c] per-batch stride
    const long long sCI = (long long)CH * HW;   // [c][i] per-batch stride
    const long long sW  = (long long)HW * HW;

    // 1) GroupNorm (stats + fused g_l zero) + weight conversion + apply/transpose
    gn_stats<<<BATCH * NGROUP, 256>>>(x);
    conv_w<<<CH * CH / 256, 256>>>(wq, wk, wv, wp);
    gn_apply_t<<<dim3(HW / 32, CH / 64, BATCH), 256>>>(x, gs, gb);

    // 2) Q and K fused (grid.x = 4; x>>1 selects Q vs K halves of wq|wk)
    dim3 gQK(4, HW / 128, BATCH);
    mma_gemm<7><<<gQK, 256, GEMM_SMEM_BYTES>>>(
        p_ofT, p_w16, p_q, HW, CH, CH, sIC, 0, sIC, 1.0f, bq, nullptr,
        nullptr, p_k, bk);
    // V: [c][j] = W x OF + bias[m]
    dim3 gV(HW / 128, CH / 128, BATCH);
    mma_gemm<2><<<gV, 256, GEMM_SMEM_BYTES>>>(p_w16 + 2 * CH * CH, p_ofT, p_v, CH, HW, CH, 0, sIC, sCI, 1.0f, bv, nullptr);

    // 3) scores -> expS (bf16) + row sums l  (softmax without max-subtraction)
    dim3 gS(HW / 128, HW / 128, BATCH);
    mma_gemm<5><<<gS, 256, GEMM_SMEM_BYTES>>>(p_q, p_k, p_s, HW, HW, CH, sIC, sIC, sW, 0.0625f, nullptr, nullptr, p_l);

    // 4) attn (transposed): atT[i][c] = (1/l_i) * sum_j expS[i,j] V[c,j]
    dim3 gA(CH / 128, HW / 128, BATCH);
    mma_gemm<6><<<gA, 256, GEMM_SMEM_BYTES>>>(p_s, p_v, p_atT, HW, CH, HW, sW, sCI, sIC, 1.0f, nullptr, nullptr, p_l);

    // 5) proj + bias + residual -> d_out
    dim3 gP(HW / 128, CH / 128, BATCH);
    mma_gemm<4><<<gP, 256, GEMM_SMEM_BYTES>>>(p_w16 + 3 * CH * CH, p_atT, out, CH, HW, CH, 0, sIC, sCI, 1.0f, bp, x);
}

// round 12
// speedup vs baseline: 1.5409x; 1.0051x over previous
#include <cuda_runtime.h>
#include <cuda_bf16.h>
#include <math.h>
#include <stdint.h>

#define BATCH  4
#define CH     256
#define NGROUP 32
#define HW     4096
#define GEPS   1e-6f
#define STAGES 3
#define STAGE_BYTES 32768u

typedef __nv_bfloat16 bf16;

// ---------------- scratch (device globals; no allocation allowed) -------------
__device__ bf16  g_ofT[(size_t)BATCH * HW * CH];   // GN output, transposed [b][i][c]
__device__ bf16  g_q  [(size_t)BATCH * HW * CH];   // Q  [b][i][c]
__device__ bf16  g_k  [(size_t)BATCH * HW * CH];   // K  [b][j][c]
__device__ bf16  g_v  [(size_t)BATCH * CH * HW];   // V  [b][c][j]
__device__ bf16  g_atT[(size_t)BATCH * HW * CH];   // attn out transposed [b][i][c]
__device__ bf16  g_s  [(size_t)BATCH * HW * HW];   // expS bf16 (134MB)
__device__ bf16  g_w16[4 * CH * CH];               // bf16 weights: wq|wk|wv|wp
__device__ float g_l  [BATCH * HW];                // softmax row sums (atomic)
__device__ float g_mean[BATCH * NGROUP];
__device__ float g_rstd[BATCH * NGROUP];

// ---------------- GroupNorm: stats (+ zero g_l slice) ---------------------------
__global__ void __launch_bounds__(256) gn_stats(const float* __restrict__ x) {
    const int bg = blockIdx.x;                       // 0..127
    const float* p = x + (size_t)bg * (CH / NGROUP) * HW;
    const int tid = threadIdx.x;

    if (tid < 128) g_l[bg * 128 + tid] = 0.f;        // fused zero_l (BATCH*HW = 128*128)

    float s = 0.f, s2 = 0.f;
    const int n4 = (CH / NGROUP) * HW / 4;
    for (int i = tid; i < n4; i += 256) {
        float4 v = ((const float4*)p)[i];
        s  += v.x + v.y + v.z + v.w;
        s2 += v.x * v.x + v.y * v.y + v.z * v.z + v.w * v.w;
    }
    __shared__ float red[64];
    #pragma unroll
    for (int o = 16; o; o >>= 1) {
        s  += __shfl_xor_sync(0xffffffffu, s,  o);
        s2 += __shfl_xor_sync(0xffffffffu, s2, o);
    }
    if ((tid & 31) == 0) { red[tid >> 5] = s; red[32 + (tid >> 5)] = s2; }
    __syncthreads();
    if (tid == 0) {
        float ts = 0.f, ts2 = 0.f;
        #pragma unroll
        for (int w = 0; w < 8; w++) { ts += red[w]; ts2 += red[32 + w]; }
        const float inv_n = 1.0f / ((CH / NGROUP) * HW);
        float mean = ts * inv_n;
        float var  = ts2 * inv_n - mean * mean;
        g_mean[bg] = mean;
        g_rstd[bg] = rsqrtf(var + GEPS);
    }
}

// ---------------- GroupNorm apply + transpose -> bf16 OF^T [b][i][c] -----------
// 32i x 64c tiles; loads and stores both fully 128B-coalesced.
__global__ void __launch_bounds__(256) gn_apply_t(const float* __restrict__ x,
                                                  const float* __restrict__ gs,
                                                  const float* __restrict__ gb) {
    __shared__ float tile[64][33];                   // [c_local][i_local]
    const int i0 = blockIdx.x * 32, c0 = blockIdx.y * 64, b = blockIdx.z;
    const int tid = threadIdx.x;
    const int il = tid & 31, cbase = tid >> 5;       // 8 c-rows per pass

    #pragma unroll
    for (int cc = 0; cc < 8; cc++) {
        int cl = cbase + cc * 8;                     // 0..63
        int c = c0 + cl;
        int bg = b * NGROUP + (c >> 3);              // 8 channels per group
        float r = g_rstd[bg];
        float a = gs[c] * r;
        float t = gb[c] - g_mean[bg] * a;
        float v = x[((size_t)b * CH + c) * HW + i0 + il];
        tile[cl][il] = v * a + t;
    }
    __syncthreads();

    #pragma unroll
    for (int h = 0; h < 4; h++) {
        int p = tid + h * 256;                       // 1024 bf162 slots
        int ir = p >> 5, cl = (p & 31) * 2;          // row 0..31, col 0..62
        __nv_bfloat162 o;
        o.x = __float2bfloat16_rn(tile[cl][ir]);
        o.y = __float2bfloat16_rn(tile[cl + 1][ir]);
        *(__nv_bfloat162*)(&g_ofT[((size_t)b * HW + i0 + ir) * CH + c0 + cl]) = o;
    }
}

// ---------------- weights -> bf16 ----------------------------------------------
__global__ void __launch_bounds__(256) conv_w(const float* __restrict__ wq,
                                              const float* __restrict__ wk,
                                              const float* __restrict__ wv,
                                              const float* __restrict__ wp) {
    int i = blockIdx.x * 256 + threadIdx.x;
    if (i >= CH * CH) return;
    g_w16[0 * CH * CH + i] = __float2bfloat16_rn(wq[i]);
    g_w16[1 * CH * CH + i] = __float2bfloat16_rn(wk[i]);
    g_w16[2 * CH * CH + i] = __float2bfloat16_rn(wv[i]);
    g_w16[3 * CH * CH + i] = __float2bfloat16_rn(wp[i]);
}

// ---------------- bf16 tensor-core GEMM (mma.sync HMMA) -------------------------
// D[m][n] = scale * sum_k A[m][k]*B[n][k] (+ epilogue)
// A: [M][K] bf16 k-contig, B: [N][K] bf16 k-contig.
// EPI 2: bf16 out*scale + bias[m].
// EPI 4: fp32 out + bias[m] + resid[m][n].
// EPI 5: bf16 out = exp(acc*scale); atomicAdd per-row sums into lptr.
// EPI 6: bf16 out = acc / lptr[row].
// EPI 7: fused Q|K projection: grid.x=4; x>>1 selects {Dv,bias} vs {Dv2,bias2};
//        B rows addressed over the concatenated 512-row weight; bias[n] epilogue.
// CTA 128x128, 8 warps (2m x 4n), warp tile 64x32, mma m16n8k16.
// Pipeline: BK=64 per stage (two 32-col sub-chunks), STAGES=3, ONE sync per 64-K
// (halves barrier/WAITG count vs BK=32). smem 96KB/CTA -> 2 CTAs/SM.
// __launch_bounds__(256, 2) pins regs <= 128 so all epilogue variants keep 2 CTAs/SM.

__device__ __forceinline__ unsigned swz(int m, int c) {  // 16B-chunk index in [128][32]bf16 tile
    return (unsigned)((m << 2) + (c ^ ((m >> 1) & 3)));
}

#define CP16(dst_u32, src_ptr) \
    asm volatile("cp.async.cg.shared.global [%0], [%1], 16;\n" :: "r"(dst_u32), "l"(src_ptr))
#define LDMX4(r0, r1, r2, r3, addr) \
    asm volatile("ldmatrix.sync.aligned.m8n8.x4.shared.b16 {%0,%1,%2,%3}, [%4];\n" \
                 : "=r"(r0), "=r"(r1), "=r"(r2), "=r"(r3) : "r"(addr))
#define MMA16816(c0, c1, c2, c3, a0, a1, a2, a3, b0, b1) \
    asm volatile("mma.sync.aligned.m16n8k16.row.col.f32.bf16.bf16.f32 " \
                 "{%0,%1,%2,%3}, {%4,%5,%6,%7}, {%8,%9}, {%0,%1,%2,%3};\n" \
                 : "+f"(c0), "+f"(c1), "+f"(c2), "+f"(c3) \
                 : "r"(a0), "r"(a1), "r"(a2), "r"(a3), "r"(b0), "r"(b1))
#define COMMIT() asm volatile("cp.async.commit_group;\n")
#define WAITG(n) asm volatile("cp.async.wait_group %0;\n" :: "n"(n))

#define GEMM_SMEM_BYTES (STAGES * STAGE_BYTES)

template<int EPI>
__global__ void __launch_bounds__(256, 2) mma_gemm(
    const bf16* __restrict__ A, const bf16* __restrict__ B,
    void* __restrict__ Dv, int M, int N, int K,
    long long sA, long long sB, long long sD, float scale,
    const float* __restrict__ bias, const float* __restrict__ resid,
    float* __restrict__ lptr = nullptr,
    void* __restrict__ Dv2 = nullptr, const float* __restrict__ bias2 = nullptr)
{
    extern __shared__ __align__(16) unsigned char sm[];   // STAGES x [sub0: A|B, sub1: A|B]
    const int bz = blockIdx.z;
    A += (size_t)bz * sA;
    B += (size_t)bz * sB;
    const int m0 = blockIdx.y * 128;
    int n0;                                               // output column base
    if (EPI == 7) {
        B += (size_t)(blockIdx.x * 128) * K;              // rows into concatenated wq|wk
        if (blockIdx.x >> 1) { Dv = Dv2; bias = bias2; }
        n0 = (blockIdx.x & 1) * 128;
    } else {
        n0 = blockIdx.x * 128;
        B += (size_t)n0 * K;
    }
    const int tid = threadIdx.x, lane = tid & 31, warp = tid >> 5;
    const int wm = warp >> 2, wn = warp & 3;

    const unsigned smbase = (unsigned)__cvta_generic_to_shared(sm);

    const int lm = tid >> 2, lc = tid & 3;
    const bf16* gA0 = A + (size_t)(m0 + lm)      * K + lc * 8;
    const bf16* gA1 = A + (size_t)(m0 + lm + 64) * K + lc * 8;
    const bf16* gB0 = B + (size_t)(lm)      * K + lc * 8;
    const bf16* gB1 = B + (size_t)(lm + 64) * K + lc * 8;
    const unsigned dA0 = swz(lm, lc) * 16u;
    const unsigned dA1 = swz(lm + 64, lc) * 16u;
    const unsigned dB0 = 8192u + swz(lm, lc) * 16u;
    const unsigned dB1 = 8192u + swz(lm + 64, lc) * 16u;

    unsigned aOff[4], bOff[2];
    {
        int r = wm * 64 + (lane & 15);
        int c0 = lane >> 4;
        #pragma unroll
        for (int mt = 0; mt < 4; mt++) aOff[mt] = swz(r + mt * 16, c0) * 16u;
    }
    {
        int r = wn * 32 + ((lane >> 4) << 3) + (lane & 7);
        int c0 = (lane >> 3) & 1;
        #pragma unroll
        for (int p = 0; p < 2; p++) bOff[p] = 8192u + swz(r + p * 16, c0) * 16u;
    }

    float acc[4][4][4];
    #pragma unroll
    for (int i = 0; i < 4; i++)
        #pragma unroll
        for (int j = 0; j < 4; j++)
            #pragma unroll
            for (int r = 0; r < 4; r++) acc[i][j][r] = 0.f;

    const int iters = K >> 6;           // BK=64; K >= 256 -> iters >= 4 > STAGES-1

    // prologue: fill stages 0..STAGES-2 (each stage = two 32-col sub-chunks)
    #pragma unroll
    for (int s = 0; s < STAGES - 1; ++s) {
        unsigned st = smbase + (unsigned)s * STAGE_BYTES;
        #pragma unroll
        for (int sub = 0; sub < 2; ++sub) {
            unsigned sp = st + (unsigned)sub * 16384u;
            int k0 = (s * 2 + sub) << 5;
            CP16(sp + dA0, gA0 + k0); CP16(sp + dA1, gA1 + k0);
            CP16(sp + dB0, gB0 + k0); CP16(sp + dB1, gB1 + k0);
        }
        COMMIT();
    }

    int cs = 0;                                      // consuming stage index
    for (int it = 0; it < iters; ++it) {
        WAITG(STAGES - 2);
        __syncthreads();
        {
            int pf = it + STAGES - 1;
            if (pf < iters) {
                // fill the stage freed last iteration: (cs + STAGES - 1) % STAGES
                int fs = cs - 1; if (fs < 0) fs = STAGES - 1;
                unsigned st = smbase + (unsigned)fs * STAGE_BYTES;
                #pragma unroll
                for (int sub = 0; sub < 2; ++sub) {
                    unsigned sp = st + (unsigned)sub * 16384u;
                    int k0 = (pf * 2 + sub) << 5;
                    CP16(sp + dA0, gA0 + k0); CP16(sp + dA1, gA1 + k0);
                    CP16(sp + dB0, gB0 + k0); CP16(sp + dB1, gB1 + k0);
                }
            }
            COMMIT();
        }

        const unsigned sb0 = smbase + (unsigned)cs * STAGE_BYTES;
        #pragma unroll
        for (int sub = 0; sub < 2; ++sub) {
            const unsigned sb = sb0 + (unsigned)sub * 16384u;
            #pragma unroll
            for (int ks = 0; ks < 2; ++ks) {
                const unsigned kx = (unsigned)ks * 32u;
                unsigned a[4][4], b[2][4];
                #pragma unroll
                for (int mt = 0; mt < 4; mt++)
                    LDMX4(a[mt][0], a[mt][1], a[mt][2], a[mt][3], sb + (aOff[mt] ^ kx));
                #pragma unroll
                for (int p = 0; p < 2; p++)
                    LDMX4(b[p][0], b[p][1], b[p][2], b[p][3], sb + (bOff[p] ^ kx));

                #pragma unroll
                for (int mt = 0; mt < 4; mt++) {
                    #pragma unroll
                    for (int nt = 0; nt < 4; nt++) {
                        const int p = nt >> 1, h = (nt & 1) << 1;
                        MMA16816(acc[mt][nt][0], acc[mt][nt][1], acc[mt][nt][2], acc[mt][nt][3],
                                 a[mt][0], a[mt][1], a[mt][2], a[mt][3],
                                 b[p][h + 0], b[p][h + 1]);
                    }
                }
            }
        }
        if (++cs == STAGES) cs = 0;
    }

    // epilogue: c0 @(r,cc) c1 @(r,cc+1) c2 @(r+8,cc) c3 @(r+8,cc+1)
    const int row = m0 + wm * 64 + (lane >> 2);
    const int col = n0 + wn * 32 + (lane & 3) * 2;

    if (EPI == 4) {
        float* D = (float*)Dv + (size_t)bz * sD;
        const float* R = resid + (size_t)bz * sD;
        #pragma unroll
        for (int mt = 0; mt < 4; mt++) {
            #pragma unroll
            for (int nt = 0; nt < 4; nt++) {
                int r = row + mt * 16, cc = col + nt * 8;
                float b0 = bias[r], b1 = bias[r + 8];
                float2 v0 = { acc[mt][nt][0] + b0, acc[mt][nt][1] + b0 };
                float2 v1 = { acc[mt][nt][2] + b1, acc[mt][nt][3] + b1 };
                float2 r0 = *(const float2*)(&R[(size_t)r * N + cc]);
                float2 r1 = *(const float2*)(&R[(size_t)(r + 8) * N + cc]);
                v0.x += r0.x; v0.y += r0.y; v1.x += r1.x; v1.y += r1.y;
                *(float2*)(&D[(size_t)r * N + cc])       = v0;
                *(float2*)(&D[(size_t)(r + 8) * N + cc]) = v1;
            }
        }
    } else if (EPI == 5) {
        // exp epilogue + row-sum atomics (scores). M == HW, rows are i.
        bf16* D = (bf16*)Dv + (size_t)bz * sD;
        float* lrow = lptr + (size_t)bz * M;
        #pragma unroll
        for (int mt = 0; mt < 4; mt++) {
            const int r = row + mt * 16;
            float s0 = 0.f, s1 = 0.f;
            #pragma unroll
            for (int nt = 0; nt < 4; nt++) {
                int cc = col + nt * 8;
                float e0 = __expf(acc[mt][nt][0] * scale);
                float e1 = __expf(acc[mt][nt][1] * scale);
                float e2 = __expf(acc[mt][nt][2] * scale);
                float e3 = __expf(acc[mt][nt][3] * scale);
                s0 += e0 + e1;  s1 += e2 + e3;
                __nv_bfloat162 o0 = __floats2bfloat162_rn(e0, e1);
                __nv_bfloat162 o1 = __floats2bfloat162_rn(e2, e3);
                *(__nv_bfloat162*)(&D[(size_t)r * N + cc])       = o0;
                *(__nv_bfloat162*)(&D[(size_t)(r + 8) * N + cc]) = o1;
            }
            s0 += __shfl_xor_sync(0xffffffffu, s0, 1);
            s0 += __shfl_xor_sync(0xffffffffu, s0, 2);
            s1 += __shfl_xor_sync(0xffffffffu, s1, 1);
            s1 += __shfl_xor_sync(0xffffffffu, s1, 2);
            if ((lane & 3) == 0) {
                atomicAdd(&lrow[r],     s0);
                atomicAdd(&lrow[r + 8], s1);
            }
        }
    } else if (EPI == 6) {
        // divide-by-rowsum epilogue (attn). M == HW, rows are i.
        bf16* D = (bf16*)Dv + (size_t)bz * sD;
        const float* lrow = lptr + (size_t)bz * M;
        #pragma unroll
        for (int mt = 0; mt < 4; mt++) {
            const int r = row + mt * 16;
            const float inv0 = 1.0f / lrow[r];
            const float inv1 = 1.0f / lrow[r + 8];
            #pragma unroll
            for (int nt = 0; nt < 4; nt++) {
                int cc = col + nt * 8;
                __nv_bfloat162 o0 = __floats2bfloat162_rn(acc[mt][nt][0] * inv0,
                                                          acc[mt][nt][1] * inv0);
                __nv_bfloat162 o1 = __floats2bfloat162_rn(acc[mt][nt][2] * inv1,
                                                          acc[mt][nt][3] * inv1);
                *(__nv_bfloat162*)(&D[(size_t)r * N + cc])       = o0;
                *(__nv_bfloat162*)(&D[(size_t)(r + 8) * N + cc]) = o1;
            }
        }
    } else {
        // EPI 2 (bias[m]) and EPI 7 (bias[n])
        bf16* D = (bf16*)Dv + (size_t)bz * sD;
        #pragma unroll
        for (int mt = 0; mt < 4; mt++) {
            #pragma unroll
            for (int nt = 0; nt < 4; nt++) {
                int r = row + mt * 16, cc = col + nt * 8;
                float bn0 = 0.f, bn1 = 0.f, bm0 = 0.f, bm1 = 0.f;
                if (EPI == 7) { bn0 = bias[cc]; bn1 = bias[cc + 1]; }
                if (EPI == 2) { bm0 = bias[r];  bm1 = bias[r + 8]; }
                __nv_bfloat162 o0, o1;
                o0.x = __float2bfloat16_rn(acc[mt][nt][0] * scale + bn0 + bm0);
                o0.y = __float2bfloat16_rn(acc[mt][nt][1] * scale + bn1 + bm0);
                o1.x = __float2bfloat16_rn(acc[mt][nt][2] * scale + bn0 + bm1);
                o1.y = __float2bfloat16_rn(acc[mt][nt][3] * scale + bn1 + bm1);
                *(__nv_bfloat162*)(&D[(size_t)r * N + cc])       = o0;
                *(__nv_bfloat162*)(&D[(size_t)(r + 8) * N + cc]) = o1;
            }
        }
    }
}

// ---------------- launch --------------------------------------------------------
extern "C" void kernel_launch(void* const* d_in, const int* in_sizes, int n_in,
                              void* d_out, int out_size) {
    const float* x  = (const float*)d_in[0];
    const float* gs = (const float*)d_in[1];
    const float* gb = (const float*)d_in[2];
    const float* wq = (const float*)d_in[3];
    const float* bq = (const float*)d_in[4];
    const float* wk = (const float*)d_in[5];
    const float* bk = (const float*)d_in[6];
    const float* wv = (const float*)d_in[7];
    const float* bv = (const float*)d_in[8];
    const float* wp = (const float*)d_in[9];
    const float* bp = (const float*)d_in[10];
    float* out = (float*)d_out;

    bf16 *p_ofT, *p_q, *p_k, *p_v, *p_atT, *p_s, *p_w16;
    float *p_l;
    cudaGetSymbolAddress((void**)&p_ofT, g_ofT);
    cudaGetSymbolAddress((void**)&p_q,   g_q);
    cudaGetSymbolAddress((void**)&p_k,   g_k);
    cudaGetSymbolAddress((void**)&p_v,   g_v);
    cudaGetSymbolAddress((void**)&p_atT, g_atT);
    cudaGetSymbolAddress((void**)&p_s,   g_s);
    cudaGetSymbolAddress((void**)&p_w16, g_w16);
    cudaGetSymbolAddress((void**)&p_l,   g_l);

    cudaFuncSetAttribute(mma_gemm<2>, cudaFuncAttributeMaxDynamicSharedMemorySize, GEMM_SMEM_BYTES);
    cudaFuncSetAttribute(mma_gemm<4>, cudaFuncAttributeMaxDynamicSharedMemorySize, GEMM_SMEM_BYTES);
    cudaFuncSetAttribute(mma_gemm<5>, cudaFuncAttributeMaxDynamicSharedMemorySize, GEMM_SMEM_BYTES);
    cudaFuncSetAttribute(mma_gemm<6>, cudaFuncAttributeMaxDynamicSharedMemorySize, GEMM_SMEM_BYTES);
    cudaFuncSetAttribute(mma_gemm<7>, cudaFuncAttributeMaxDynamicSharedMemorySize, GEMM_SMEM_BYTES);

    const long long sIC = (long long)HW * CH;   // [i][c] per-batch stride
    const long long sCI = (long long)CH * HW;   // [c][i] per-batch stride
    const long long sW  = (long long)HW * HW;

    // 1) GroupNorm (stats + fused g_l zero) + weight conversion + apply/transpose
    gn_stats<<<BATCH * NGROUP, 256>>>(x);
    conv_w<<<CH * CH / 256, 256>>>(wq, wk, wv, wp);
    gn_apply_t<<<dim3(HW / 32, CH / 64, BATCH), 256>>>(x, gs, gb);

    // 2) Q and K fused (grid.x = 4; x>>1 selects Q vs K halves of wq|wk)
    dim3 gQK(4, HW / 128, BATCH);
    mma_gemm<7><<<gQK, 256, GEMM_SMEM_BYTES>>>(
        p_ofT, p_w16, p_q, HW, CH, CH, sIC, 0, sIC, 1.0f, bq, nullptr,
        nullptr, p_k, bk);
    // V: [c][j] = W x OF + bias[m]
    dim3 gV(HW / 128, CH / 128, BATCH);
    mma_gemm<2><<<gV, 256, GEMM_SMEM_BYTES>>>(p_w16 + 2 * CH * CH, p_ofT, p_v, CH, HW, CH, 0, sIC, sCI, 1.0f, bv, nullptr);

    // 3) scores -> expS (bf16) + row sums l  (softmax without max-subtraction)
    dim3 gS(HW / 128, HW / 128, BATCH);
    mma_gemm<5><<<gS, 256, GEMM_SMEM_BYTES>>>(p_q, p_k, p_s, HW, HW, CH, sIC, sIC, sW, 0.0625f, nullptr, nullptr, p_l);

    // 4) attn (transposed): atT[i][c] = (1/l_i) * sum_j expS[i,j] V[c,j]
    dim3 gA(CH / 128, HW / 128, BATCH);
    mma_gemm<6><<<gA, 256, GEMM_SMEM_BYTES>>>(p_s, p_v, p_atT, HW, CH, HW, sW, sCI, sIC, 1.0f, nullptr, nullptr, p_l);

    // 5) proj + bias + residual -> d_out
    dim3 gP(HW / 128, CH / 128, BATCH);
    mma_gemm<4><<<gP, 256, GEMM_SMEM_BYTES>>>(p_w16 + 3 * CH * CH, p_atT, out, CH, HW, CH, 0, sIC, sCI, 1.0f, bp, x);
}

// round 13
// speedup vs baseline: 1.5427x; 1.0012x over previous
#include <cuda_runtime.h>
#include <cuda_bf16.h>
#include <math.h>
#include <stdint.h>

#define BATCH  4
#define CH     256
#define NGROUP 32
#define HW     4096
#define GEPS   1e-6f
#define STAGES 3
#define STAGE_BYTES 32768u

typedef __nv_bfloat16 bf16;

// ---------------- scratch (device globals; no allocation allowed) -------------
__device__ bf16  g_ofT[(size_t)BATCH * HW * CH];   // GN output, transposed [b][i][c]
__device__ bf16  g_q  [(size_t)BATCH * HW * CH];   // Q  [b][i][c]
__device__ bf16  g_k  [(size_t)BATCH * HW * CH];   // K  [b][j][c]
__device__ bf16  g_v  [(size_t)BATCH * CH * HW];   // V  [b][c][j]
__device__ bf16  g_atT[(size_t)BATCH * HW * CH];   // attn out transposed [b][i][c]
__device__ bf16  g_s  [(size_t)BATCH * HW * HW];   // expS bf16 (134MB)
__device__ bf16  g_w16[4 * CH * CH];               // bf16 weights: wq|wk|wv|wp
__device__ float g_l  [BATCH * HW];                // softmax row sums (atomic)
__device__ float g_sum [BATCH * NGROUP];           // GN partial sums (atomic)
__device__ float g_sum2[BATCH * NGROUP];

// ---------------- weights -> bf16 (+ zero g_l / g_sum / g_sum2) -----------------
__global__ void __launch_bounds__(256) conv_w(const float* __restrict__ wq,
                                              const float* __restrict__ wk,
                                              const float* __restrict__ wv,
                                              const float* __restrict__ wp) {
    int i = blockIdx.x * 256 + threadIdx.x;
    if (i < BATCH * NGROUP) { g_sum[i] = 0.f; g_sum2[i] = 0.f; }
    if (i < BATCH * HW) g_l[i] = 0.f;                // 16384 < 65536 threads
    if (i >= CH * CH) return;
    g_w16[0 * CH * CH + i] = __float2bfloat16_rn(wq[i]);
    g_w16[1 * CH * CH + i] = __float2bfloat16_rn(wk[i]);
    g_w16[2 * CH * CH + i] = __float2bfloat16_rn(wv[i]);
    g_w16[3 * CH * CH + i] = __float2bfloat16_rn(wp[i]);
}

// ---------------- GroupNorm: stats (8 slices/group, atomic partials) ------------
__global__ void __launch_bounds__(256) gn_stats(const float* __restrict__ x) {
    const int blk = blockIdx.x;                      // 0..1023
    const int bg = blk >> 3, slice = blk & 7;
    const float* p = x + (size_t)bg * (CH / NGROUP) * HW + (size_t)slice * 4096;
    const int tid = threadIdx.x;

    float s = 0.f, s2 = 0.f;
    #pragma unroll
    for (int i = 0; i < 4; i++) {                    // 1024 float4 per slice
        float4 v = ((const float4*)p)[tid + i * 256];
        s  += v.x + v.y + v.z + v.w;
        s2 += v.x * v.x + v.y * v.y + v.z * v.z + v.w * v.w;
    }
    __shared__ float red[64];
    #pragma unroll
    for (int o = 16; o; o >>= 1) {
        s  += __shfl_xor_sync(0xffffffffu, s,  o);
        s2 += __shfl_xor_sync(0xffffffffu, s2, o);
    }
    if ((tid & 31) == 0) { red[tid >> 5] = s; red[32 + (tid >> 5)] = s2; }
    __syncthreads();
    if (tid == 0) {
        float ts = 0.f, ts2 = 0.f;
        #pragma unroll
        for (int w = 0; w < 8; w++) { ts += red[w]; ts2 += red[32 + w]; }
        atomicAdd(&g_sum[bg],  ts);
        atomicAdd(&g_sum2[bg], ts2);
    }
}

// ---------------- GroupNorm apply + transpose -> bf16 OF^T [b][i][c] -----------
// 32i x 64c tiles; loads and stores both fully 128B-coalesced.
// mean/rstd derived inline from g_sum/g_sum2.
__global__ void __launch_bounds__(256) gn_apply_t(const float* __restrict__ x,
                                                  const float* __restrict__ gs,
                                                  const float* __restrict__ gb) {
    __shared__ float tile[64][33];                   // [c_local][i_local]
    const int i0 = blockIdx.x * 32, c0 = blockIdx.y * 64, b = blockIdx.z;
    const int tid = threadIdx.x;
    const int il = tid & 31, cbase = tid >> 5;       // 8 c-rows per pass
    const float inv_n = 1.0f / ((CH / NGROUP) * HW);

    #pragma unroll
    for (int cc = 0; cc < 8; cc++) {
        int cl = cbase + cc * 8;                     // 0..63
        int c = c0 + cl;
        int bg = b * NGROUP + (c >> 3);              // 8 channels per group
        float mean = g_sum[bg] * inv_n;
        float var  = g_sum2[bg] * inv_n - mean * mean;
        float r = rsqrtf(var + GEPS);
        float a = gs[c] * r;
        float t = gb[c] - mean * a;
        float v = x[((size_t)b * CH + c) * HW + i0 + il];
        tile[cl][il] = v * a + t;
    }
    __syncthreads();

    #pragma unroll
    for (int h = 0; h < 4; h++) {
        int p = tid + h * 256;                       // 1024 bf162 slots
        int ir = p >> 5, cl = (p & 31) * 2;          // row 0..31, col 0..62
        __nv_bfloat162 o;
        o.x = __float2bfloat16_rn(tile[cl][ir]);
        o.y = __float2bfloat16_rn(tile[cl + 1][ir]);
        *(__nv_bfloat162*)(&g_ofT[((size_t)b * HW + i0 + ir) * CH + c0 + cl]) = o;
    }
}

// ---------------- bf16 tensor-core GEMM (mma.sync HMMA) -------------------------
// D[m][n] = scale * sum_k A[m][k]*B[n][k] (+ epilogue)
// A: [M][K] bf16 k-contig, B: [N][K] bf16 k-contig.
// EPI 2: bf16 out*scale + bias[m].
// EPI 4: fp32 out + bias[m] + resid[m][n].
// EPI 5: bf16 out = exp(acc*scale); atomicAdd per-row sums into lptr.
// EPI 6: bf16 out = acc / lptr[row].
// EPI 7: fused Q|K projection: grid.x=4; x>>1 selects {Dv,bias} vs {Dv2,bias2};
//        B rows addressed over the concatenated 512-row weight; bias[n] epilogue.
// CTA 128x128, 8 warps (2m x 4n), warp tile 64x32, mma m16n8k16.
// Pipeline: BK=64 per stage (two 32-col sub-chunks), STAGES=3, one sync per 64-K.
// __launch_bounds__(256, 2) pins regs <= 128 so all epilogue variants keep 2 CTAs/SM.

__device__ __forceinline__ unsigned swz(int m, int c) {  // 16B-chunk index in [128][32]bf16 tile
    return (unsigned)((m << 2) + (c ^ ((m >> 1) & 3)));
}

#define CP16(dst_u32, src_ptr) \
    asm volatile("cp.async.cg.shared.global [%0], [%1], 16;\n" :: "r"(dst_u32), "l"(src_ptr))
#define LDMX4(r0, r1, r2, r3, addr) \
    asm volatile("ldmatrix.sync.aligned.m8n8.x4.shared.b16 {%0,%1,%2,%3}, [%4];\n" \
                 : "=r"(r0), "=r"(r1), "=r"(r2), "=r"(r3) : "r"(addr))
#define MMA16816(c0, c1, c2, c3, a0, a1, a2, a3, b0, b1) \
    asm volatile("mma.sync.aligned.m16n8k16.row.col.f32.bf16.bf16.f32 " \
                 "{%0,%1,%2,%3}, {%4,%5,%6,%7}, {%8,%9}, {%0,%1,%2,%3};\n" \
                 : "+f"(c0), "+f"(c1), "+f"(c2), "+f"(c3) \
                 : "r"(a0), "r"(a1), "r"(a2), "r"(a3), "r"(b0), "r"(b1))
#define COMMIT() asm volatile("cp.async.commit_group;\n")
#define WAITG(n) asm volatile("cp.async.wait_group %0;\n" :: "n"(n))

#define GEMM_SMEM_BYTES (STAGES * STAGE_BYTES)

template<int EPI>
__global__ void __launch_bounds__(256, 2) mma_gemm(
    const bf16* __restrict__ A, const bf16* __restrict__ B,
    void* __restrict__ Dv, int M, int N, int K,
    long long sA, long long sB, long long sD, float scale,
    const float* __restrict__ bias, const float* __restrict__ resid,
    float* __restrict__ lptr = nullptr,
    void* __restrict__ Dv2 = nullptr, const float* __restrict__ bias2 = nullptr)
{
    extern __shared__ __align__(16) unsigned char sm[];   // STAGES x [sub0: A|B, sub1: A|B]
    const int bz = blockIdx.z;
    A += (size_t)bz * sA;
    B += (size_t)bz * sB;
    const int m0 = blockIdx.y * 128;
    int n0;                                               // output column base
    if (EPI == 7) {
        B += (size_t)(blockIdx.x * 128) * K;              // rows into concatenated wq|wk
        if (blockIdx.x >> 1) { Dv = Dv2; bias = bias2; }
        n0 = (blockIdx.x & 1) * 128;
    } else {
        n0 = blockIdx.x * 128;
        B += (size_t)n0 * K;
    }
    const int tid = threadIdx.x, lane = tid & 31, warp = tid >> 5;
    const int wm = warp >> 2, wn = warp & 3;

    const unsigned smbase = (unsigned)__cvta_generic_to_shared(sm);

    const int lm = tid >> 2, lc = tid & 3;
    const bf16* gA0 = A + (size_t)(m0 + lm)      * K + lc * 8;
    const bf16* gA1 = A + (size_t)(m0 + lm + 64) * K + lc * 8;
    const bf16* gB0 = B + (size_t)(lm)      * K + lc * 8;
    const bf16* gB1 = B + (size_t)(lm + 64) * K + lc * 8;
    const unsigned dA0 = swz(lm, lc) * 16u;
    const unsigned dA1 = swz(lm + 64, lc) * 16u;
    const unsigned dB0 = 8192u + swz(lm, lc) * 16u;
    const unsigned dB1 = 8192u + swz(lm + 64, lc) * 16u;

    unsigned aOff[4], bOff[2];
    {
        int r = wm * 64 + (lane & 15);
        int c0 = lane >> 4;
        #pragma unroll
        for (int mt = 0; mt < 4; mt++) aOff[mt] = swz(r + mt * 16, c0) * 16u;
    }
    {
        int r = wn * 32 + ((lane >> 4) << 3) + (lane & 7);
        int c0 = (lane >> 3) & 1;
        #pragma unroll
        for (int p = 0; p < 2; p++) bOff[p] = 8192u + swz(r + p * 16, c0) * 16u;
    }

    float acc[4][4][4];
    #pragma unroll
    for (int i = 0; i < 4; i++)
        #pragma unroll
        for (int j = 0; j < 4; j++)
            #pragma unroll
            for (int r = 0; r < 4; r++) acc[i][j][r] = 0.f;

    const int iters = K >> 6;           // BK=64; K >= 256 -> iters >= 4 > STAGES-1

    // prologue: fill stages 0..STAGES-2 (each stage = two 32-col sub-chunks)
    #pragma unroll
    for (int s = 0; s < STAGES - 1; ++s) {
        unsigned st = smbase + (unsigned)s * STAGE_BYTES;
        #pragma unroll
        for (int sub = 0; sub < 2; ++sub) {
            unsigned sp = st + (unsigned)sub * 16384u;
            int k0 = (s * 2 + sub) << 5;
            CP16(sp + dA0, gA0 + k0); CP16(sp + dA1, gA1 + k0);
            CP16(sp + dB0, gB0 + k0); CP16(sp + dB1, gB1 + k0);
        }
        COMMIT();
    }

    int cs = 0;                                      // consuming stage index
    for (int it = 0; it < iters; ++it) {
        WAITG(STAGES - 2);
        __syncthreads();
        {
            int pf = it + STAGES - 1;
            if (pf < iters) {
                int fs = cs - 1; if (fs < 0) fs = STAGES - 1;
                unsigned st = smbase + (unsigned)fs * STAGE_BYTES;
                #pragma unroll
                for (int sub = 0; sub < 2; ++sub) {
                    unsigned sp = st + (unsigned)sub * 16384u;
                    int k0 = (pf * 2 + sub) << 5;
                    CP16(sp + dA0, gA0 + k0); CP16(sp + dA1, gA1 + k0);
                    CP16(sp + dB0, gB0 + k0); CP16(sp + dB1, gB1 + k0);
                }
            }
            COMMIT();
        }

        const unsigned sb0 = smbase + (unsigned)cs * STAGE_BYTES;
        #pragma unroll
        for (int sub = 0; sub < 2; ++sub) {
            const unsigned sb = sb0 + (unsigned)sub * 16384u;
            #pragma unroll
            for (int ks = 0; ks < 2; ++ks) {
                const unsigned kx = (unsigned)ks * 32u;
                unsigned a[4][4], b[2][4];
                #pragma unroll
                for (int mt = 0; mt < 4; mt++)
                    LDMX4(a[mt][0], a[mt][1], a[mt][2], a[mt][3], sb + (aOff[mt] ^ kx));
                #pragma unroll
                for (int p = 0; p < 2; p++)
                    LDMX4(b[p][0], b[p][1], b[p][2], b[p][3], sb + (bOff[p] ^ kx));

                #pragma unroll
                for (int mt = 0; mt < 4; mt++) {
                    #pragma unroll
                    for (int nt = 0; nt < 4; nt++) {
                        const int p = nt >> 1, h = (nt & 1) << 1;
                        MMA16816(acc[mt][nt][0], acc[mt][nt][1], acc[mt][nt][2], acc[mt][nt][3],
                                 a[mt][0], a[mt][1], a[mt][2], a[mt][3],
                                 b[p][h + 0], b[p][h + 1]);
                    }
                }
            }
        }
        if (++cs == STAGES) cs = 0;
    }

    // epilogue: c0 @(r,cc) c1 @(r,cc+1) c2 @(r+8,cc) c3 @(r+8,cc+1)
    const int row = m0 + wm * 64 + (lane >> 2);
    const int col = n0 + wn * 32 + (lane & 3) * 2;

    if (EPI == 4) {
        float* D = (float*)Dv + (size_t)bz * sD;
        const float* R = resid + (size_t)bz * sD;
        #pragma unroll
        for (int mt = 0; mt < 4; mt++) {
            #pragma unroll
            for (int nt = 0; nt < 4; nt++) {
                int r = row + mt * 16, cc = col + nt * 8;
                float b0 = bias[r], b1 = bias[r + 8];
                float2 v0 = { acc[mt][nt][0] + b0, acc[mt][nt][1] + b0 };
                float2 v1 = { acc[mt][nt][2] + b1, acc[mt][nt][3] + b1 };
                float2 r0 = *(const float2*)(&R[(size_t)r * N + cc]);
                float2 r1 = *(const float2*)(&R[(size_t)(r + 8) * N + cc]);
                v0.x += r0.x; v0.y += r0.y; v1.x += r1.x; v1.y += r1.y;
                *(float2*)(&D[(size_t)r * N + cc])       = v0;
                *(float2*)(&D[(size_t)(r + 8) * N + cc]) = v1;
            }
        }
    } else if (EPI == 5) {
        // exp epilogue + row-sum atomics (scores). M == HW, rows are i.
        bf16* D = (bf16*)Dv + (size_t)bz * sD;
        float* lrow = lptr + (size_t)bz * M;
        #pragma unroll
        for (int mt = 0; mt < 4; mt++) {
            const int r = row + mt * 16;
            float s0 = 0.f, s1 = 0.f;
            #pragma unroll
            for (int nt = 0; nt < 4; nt++) {
                int cc = col + nt * 8;
                float e0 = __expf(acc[mt][nt][0] * scale);
                float e1 = __expf(acc[mt][nt][1] * scale);
                float e2 = __expf(acc[mt][nt][2] * scale);
                float e3 = __expf(acc[mt][nt][3] * scale);
                s0 += e0 + e1;  s1 += e2 + e3;
                __nv_bfloat162 o0 = __floats2bfloat162_rn(e0, e1);
                __nv_bfloat162 o1 = __floats2bfloat162_rn(e2, e3);
                *(__nv_bfloat162*)(&D[(size_t)r * N + cc])       = o0;
                *(__nv_bfloat162*)(&D[(size_t)(r + 8) * N + cc]) = o1;
            }
            s0 += __shfl_xor_sync(0xffffffffu, s0, 1);
            s0 += __shfl_xor_sync(0xffffffffu, s0, 2);
            s1 += __shfl_xor_sync(0xffffffffu, s1, 1);
            s1 += __shfl_xor_sync(0xffffffffu, s1, 2);
            if ((lane & 3) == 0) {
                atomicAdd(&lrow[r],     s0);
                atomicAdd(&lrow[r + 8], s1);
            }
        }
    } else if (EPI == 6) {
        // divide-by-rowsum epilogue (attn). M == HW, rows are i.
        bf16* D = (bf16*)Dv + (size_t)bz * sD;
        const float* lrow = lptr + (size_t)bz * M;
        #pragma unroll
        for (int mt = 0; mt < 4; mt++) {
            const int r = row + mt * 16;
            const float inv0 = 1.0f / lrow[r];
            const float inv1 = 1.0f / lrow[r + 8];
            #pragma unroll
            for (int nt = 0; nt < 4; nt++) {
                int cc = col + nt * 8;
                __nv_bfloat162 o0 = __floats2bfloat162_rn(acc[mt][nt][0] * inv0,
                                                          acc[mt][nt][1] * inv0);
                __nv_bfloat162 o1 = __floats2bfloat162_rn(acc[mt][nt][2] * inv1,
                                                          acc[mt][nt][3] * inv1);
                *(__nv_bfloat162*)(&D[(size_t)r * N + cc])       = o0;
                *(__nv_bfloat162*)(&D[(size_t)(r + 8) * N + cc]) = o1;
            }
        }
    } else {
        // EPI 2 (bias[m]) and EPI 7 (bias[n])
        bf16* D = (bf16*)Dv + (size_t)bz * sD;
        #pragma unroll
        for (int mt = 0; mt < 4; mt++) {
            #pragma unroll
            for (int nt = 0; nt < 4; nt++) {
                int r = row + mt * 16, cc = col + nt * 8;
                float bn0 = 0.f, bn1 = 0.f, bm0 = 0.f, bm1 = 0.f;
                if (EPI == 7) { bn0 = bias[cc]; bn1 = bias[cc + 1]; }
                if (EPI == 2) { bm0 = bias[r];  bm1 = bias[r + 8]; }
                __nv_bfloat162 o0, o1;
                o0.x = __float2bfloat16_rn(acc[mt][nt][0] * scale + bn0 + bm0);
                o0.y = __float2bfloat16_rn(acc[mt][nt][1] * scale + bn1 + bm0);
                o1.x = __float2bfloat16_rn(acc[mt][nt][2] * scale + bn0 + bm1);
                o1.y = __float2bfloat16_rn(acc[mt][nt][3] * scale + bn1 + bm1);
                *(__nv_bfloat162*)(&D[(size_t)r * N + cc])       = o0;
                *(__nv_bfloat162*)(&D[(size_t)(r + 8) * N + cc]) = o1;
            }
        }
    }
}

// ---------------- launch --------------------------------------------------------
extern "C" void kernel_launch(void* const* d_in, const int* in_sizes, int n_in,
                              void* d_out, int out_size) {
    const float* x  = (const float*)d_in[0];
    const float* gs = (const float*)d_in[1];
    const float* gb = (const float*)d_in[2];
    const float* wq = (const float*)d_in[3];
    const float* bq = (const float*)d_in[4];
    const float* wk = (const float*)d_in[5];
    const float* bk = (const float*)d_in[6];
    const float* wv = (const float*)d_in[7];
    const float* bv = (const float*)d_in[8];
    const float* wp = (const float*)d_in[9];
    const float* bp = (const float*)d_in[10];
    float* out = (float*)d_out;

    bf16 *p_ofT, *p_q, *p_k, *p_v, *p_atT, *p_s, *p_w16;
    float *p_l;
    cudaGetSymbolAddress((void**)&p_ofT, g_ofT);
    cudaGetSymbolAddress((void**)&p_q,   g_q);
    cudaGetSymbolAddress((void**)&p_k,   g_k);
    cudaGetSymbolAddress((void**)&p_v,   g_v);
    cudaGetSymbolAddress((void**)&p_atT, g_atT);
    cudaGetSymbolAddress((void**)&p_s,   g_s);
    cudaGetSymbolAddress((void**)&p_w16, g_w16);
    cudaGetSymbolAddress((void**)&p_l,   g_l);

    cudaFuncSetAttribute(mma_gemm<2>, cudaFuncAttributeMaxDynamicSharedMemorySize, GEMM_SMEM_BYTES);
    cudaFuncSetAttribute(mma_gemm<4>, cudaFuncAttributeMaxDynamicSharedMemorySize, GEMM_SMEM_BYTES);
    cudaFuncSetAttribute(mma_gemm<5>, cudaFuncAttributeMaxDynamicSharedMemorySize, GEMM_SMEM_BYTES);
    cudaFuncSetAttribute(mma_gemm<6>, cudaFuncAttributeMaxDynamicSharedMemorySize, GEMM_SMEM_BYTES);
    cudaFuncSetAttribute(mma_gemm<7>, cudaFuncAttributeMaxDynamicSharedMemorySize, GEMM_SMEM_BYTES);

    const long long sIC = (long long)HW * CH;   // [i][c] per-batch stride
    const long long sCI = (long long)CH * HW;   // [c][i] per-batch stride
    const long long sW  = (long long)HW * HW;

    // 1) conv_w (also zeroes g_l/g_sum/g_sum2) -> gn_stats (atomic partials)
    //    -> gn_apply_t (derives mean/rstd inline)
    conv_w<<<CH * CH / 256, 256>>>(wq, wk, wv, wp);
    gn_stats<<<BATCH * NGROUP * 8, 256>>>(x);
    gn_apply_t<<<dim3(HW / 32, CH / 64, BATCH), 256>>>(x, gs, gb);

    // 2) Q and K fused (grid.x = 4; x>>1 selects Q vs K halves of wq|wk)
    dim3 gQK(4, HW / 128, BATCH);
    mma_gemm<7><<<gQK, 256, GEMM_SMEM_BYTES>>>(
        p_ofT, p_w16, p_q, HW, CH, CH, sIC, 0, sIC, 1.0f, bq, nullptr,
        nullptr, p_k, bk);
    // V: [c][j] = W x OF + bias[m]
    dim3 gV(HW / 128, CH / 128, BATCH);
    mma_gemm<2><<<gV, 256, GEMM_SMEM_BYTES>>>(p_w16 + 2 * CH * CH, p_ofT, p_v, CH, HW, CH, 0, sIC, sCI, 1.0f, bv, nullptr);

    // 3) scores -> expS (bf16) + row sums l  (softmax without max-subtraction)
    dim3 gS(HW / 128, HW / 128, BATCH);
    mma_gemm<5><<<gS, 256, GEMM_SMEM_BYTES>>>(p_q, p_k, p_s, HW, HW, CH, sIC, sIC, sW, 0.0625f, nullptr, nullptr, p_l);

    // 4) attn (transposed): atT[i][c] = (1/l_i) * sum_j expS[i,j] V[c,j]
    dim3 gA(CH / 128, HW / 128, BATCH);
    mma_gemm<6><<<gA, 256, GEMM_SMEM_BYTES>>>(p_s, p_v, p_atT, HW, CH, HW, sW, sCI, sIC, 1.0f, nullptr, nullptr, p_l);

    // 5) proj + bias + residual -> d_out
    dim3 gP(HW / 128, CH / 128, BATCH);
    mma_gemm<4><<<gP, 256, GEMM_SMEM_BYTES>>>(p_w16 + 3 * CH * CH, p_atT, out, CH, HW, CH, 0, sIC, sCI, 1.0f, bp, x);
}

// round 14
// speedup vs baseline: 1.5449x; 1.0014x over previous
#include <cuda_runtime.h>
#include <cuda_bf16.h>
#include <math.h>
#include <stdint.h>

#define BATCH  4
#define CH     256
#define NGROUP 32
#define HW     4096
#define GEPS   1e-6f
#define STAGES 3
#define STAGE_BYTES 32768u

typedef __nv_bfloat16 bf16;

// ---------------- scratch (device globals; no allocation allowed) -------------
__device__ bf16  g_ofT[(size_t)BATCH * HW * CH];   // GN output, transposed [b][i][c]
__device__ bf16  g_q  [(size_t)BATCH * HW * CH];   // Q  [b][i][c]
__device__ bf16  g_k  [(size_t)BATCH * HW * CH];   // K  [b][j][c]
__device__ bf16  g_v  [(size_t)BATCH * CH * HW];   // V  [b][c][j]
__device__ bf16  g_atT[(size_t)BATCH * HW * CH];   // attn out transposed [b][i][c]
__device__ bf16  g_s  [(size_t)BATCH * HW * HW];   // expS bf16 (134MB)
__device__ bf16  g_w16[4 * CH * CH];               // bf16 weights: wq|wk|wv|wp
__device__ float g_l  [BATCH * HW];                // softmax row sums (atomic)
__device__ float g_sum [BATCH * NGROUP];           // GN partial sums (atomic)
__device__ float g_sum2[BATCH * NGROUP];

// ---------------- weights -> bf16 (+ zero g_l / g_sum / g_sum2) -----------------
__global__ void __launch_bounds__(256) conv_w(const float* __restrict__ wq,
                                              const float* __restrict__ wk,
                                              const float* __restrict__ wv,
                                              const float* __restrict__ wp) {
    int i = blockIdx.x * 256 + threadIdx.x;
    if (i < BATCH * NGROUP) { g_sum[i] = 0.f; g_sum2[i] = 0.f; }
    if (i < BATCH * HW) g_l[i] = 0.f;                // 16384 < 65536 threads
    if (i >= CH * CH) return;
    g_w16[0 * CH * CH + i] = __float2bfloat16_rn(wq[i]);
    g_w16[1 * CH * CH + i] = __float2bfloat16_rn(wk[i]);
    g_w16[2 * CH * CH + i] = __float2bfloat16_rn(wv[i]);
    g_w16[3 * CH * CH + i] = __float2bfloat16_rn(wp[i]);
}

// ---------------- GroupNorm: stats (8 slices/group, atomic partials) ------------
__global__ void __launch_bounds__(256) gn_stats(const float* __restrict__ x) {
    const int blk = blockIdx.x;                      // 0..1023
    const int bg = blk >> 3, slice = blk & 7;
    const float* p = x + (size_t)bg * (CH / NGROUP) * HW + (size_t)slice * 4096;
    const int tid = threadIdx.x;

    float s = 0.f, s2 = 0.f;
    #pragma unroll
    for (int i = 0; i < 4; i++) {                    // 1024 float4 per slice
        float4 v = ((const float4*)p)[tid + i * 256];
        s  += v.x + v.y + v.z + v.w;
        s2 += v.x * v.x + v.y * v.y + v.z * v.z + v.w * v.w;
    }
    __shared__ float red[64];
    #pragma unroll
    for (int o = 16; o; o >>= 1) {
        s  += __shfl_xor_sync(0xffffffffu, s,  o);
        s2 += __shfl_xor_sync(0xffffffffu, s2, o);
    }
    if ((tid & 31) == 0) { red[tid >> 5] = s; red[32 + (tid >> 5)] = s2; }
    __syncthreads();
    if (tid == 0) {
        float ts = 0.f, ts2 = 0.f;
        #pragma unroll
        for (int w = 0; w < 8; w++) { ts += red[w]; ts2 += red[32 + w]; }
        atomicAdd(&g_sum[bg],  ts);
        atomicAdd(&g_sum2[bg], ts2);
    }
}

// ---------------- GroupNorm apply + transpose -> bf16 OF^T [b][i][c] -----------
// 32i x 64c tiles; loads and stores both fully 128B-coalesced.
__global__ void __launch_bounds__(256) gn_apply_t(const float* __restrict__ x,
                                                  const float* __restrict__ gs,
                                                  const float* __restrict__ gb) {
    __shared__ float tile[64][33];                   // [c_local][i_local]
    const int i0 = blockIdx.x * 32, c0 = blockIdx.y * 64, b = blockIdx.z;
    const int tid = threadIdx.x;
    const int il = tid & 31, cbase = tid >> 5;       // 8 c-rows per pass
    const float inv_n = 1.0f / ((CH / NGROUP) * HW);

    #pragma unroll
    for (int cc = 0; cc < 8; cc++) {
        int cl = cbase + cc * 8;                     // 0..63
        int c = c0 + cl;
        int bg = b * NGROUP + (c >> 3);              // 8 channels per group
        float mean = g_sum[bg] * inv_n;
        float var  = g_sum2[bg] * inv_n - mean * mean;
        float r = rsqrtf(var + GEPS);
        float a = gs[c] * r;
        float t = gb[c] - mean * a;
        float v = x[((size_t)b * CH + c) * HW + i0 + il];
        tile[cl][il] = v * a + t;
    }
    __syncthreads();

    #pragma unroll
    for (int h = 0; h < 4; h++) {
        int p = tid + h * 256;                       // 1024 bf162 slots
        int ir = p >> 5, cl = (p & 31) * 2;          // row 0..31, col 0..62
        __nv_bfloat162 o;
        o.x = __float2bfloat16_rn(tile[cl][ir]);
        o.y = __float2bfloat16_rn(tile[cl + 1][ir]);
        *(__nv_bfloat162*)(&g_ofT[((size_t)b * HW + i0 + ir) * CH + c0 + cl]) = o;
    }
}

// ---------------- bf16 tensor-core GEMM (mma.sync HMMA) -------------------------
// D[m][n] = scale * sum_k A[m][k]*B[n][k] (+ epilogue)
// A: [M][K] bf16 k-contig, B: [N][K] bf16 k-contig.
// EPI 4: fp32 out + bias[m] + resid[m][n].
// EPI 5: bf16 out = exp(acc*scale); atomicAdd per-row sums into lptr.
// EPI 6: bf16 out = acc / lptr[row].
// EPI 8: fused Q|K|V projection, grid.x = 6:
//   x<4: Q/K: A=ofT rows i, B=w16 rows x*128 (wq|wk concat), out [i][c], bias[n];
//        x>>1 selects {Dv(q),bias} vs {Dv2(k),bias2}.
//   x>=4: V: A=w16+2*CH*CH rows c (x-4), B=ofT rows j (grid.y), out [c][j]=lptr(cast),
//        bias[m]=resid(cast).
// CTA 128x128, 8 warps (2m x 4n), warp tile 64x32, mma m16n8k16.
// Pipeline: BK=64 per stage, STAGES=3, one sync per 64-K.
// __launch_bounds__(256, 2) pins regs <= 128 so all variants keep 2 CTAs/SM.

__device__ __forceinline__ unsigned swz(int m, int c) {  // 16B-chunk index in [128][32]bf16 tile
    return (unsigned)((m << 2) + (c ^ ((m >> 1) & 3)));
}

#define CP16(dst_u32, src_ptr) \
    asm volatile("cp.async.cg.shared.global [%0], [%1], 16;\n" :: "r"(dst_u32), "l"(src_ptr))
#define LDMX4(r0, r1, r2, r3, addr) \
    asm volatile("ldmatrix.sync.aligned.m8n8.x4.shared.b16 {%0,%1,%2,%3}, [%4];\n" \
                 : "=r"(r0), "=r"(r1), "=r"(r2), "=r"(r3) : "r"(addr))
#define MMA16816(c0, c1, c2, c3, a0, a1, a2, a3, b0, b1) \
    asm volatile("mma.sync.aligned.m16n8k16.row.col.f32.bf16.bf16.f32 " \
                 "{%0,%1,%2,%3}, {%4,%5,%6,%7}, {%8,%9}, {%0,%1,%2,%3};\n" \
                 : "+f"(c0), "+f"(c1), "+f"(c2), "+f"(c3) \
                 : "r"(a0), "r"(a1), "r"(a2), "r"(a3), "r"(b0), "r"(b1))
#define COMMIT() asm volatile("cp.async.commit_group;\n")
#define WAITG(n) asm volatile("cp.async.wait_group %0;\n" :: "n"(n))

#define GEMM_SMEM_BYTES (STAGES * STAGE_BYTES)

template<int EPI>
__global__ void __launch_bounds__(256, 2) mma_gemm(
    const bf16* __restrict__ A, const bf16* __restrict__ B,
    void* __restrict__ Dv, int M, int N, int K,
    long long sA, long long sB, long long sD, float scale,
    const float* __restrict__ bias, const float* __restrict__ resid,
    float* __restrict__ lptr = nullptr,
    void* __restrict__ Dv2 = nullptr, const float* __restrict__ bias2 = nullptr)
{
    extern __shared__ __align__(16) unsigned char sm[];   // STAGES x [sub0: A|B, sub1: A|B]
    const int bz = blockIdx.z;

    const bf16 *Ap, *Bp;
    int m0, n0, Nout;
    bf16* D8 = nullptr; const float* b8 = nullptr; bool biasOnM = false;

    if (EPI == 8) {
        if (blockIdx.x < 4) {
            // Q/K: A=ofT rows i, B=wq|wk rows (bx*128)
            Ap = A + (size_t)bz * sA + (size_t)(blockIdx.y * 128) * K;
            Bp = B + (size_t)(blockIdx.x * 128) * K;
            D8 = (bf16*)((blockIdx.x >> 1) ? Dv2 : Dv);
            b8 = (blockIdx.x >> 1) ? bias2 : bias;
            m0 = blockIdx.y * 128; n0 = (blockIdx.x & 1) * 128;
            Nout = CH; biasOnM = false;
        } else {
            // V: A = wv rows c, B = ofT rows j
            Ap = B + (size_t)(2 * CH * CH) + (size_t)((blockIdx.x - 4) * 128) * K;
            Bp = A + (size_t)bz * sA + (size_t)(blockIdx.y * 128) * K;
            D8 = (bf16*)lptr;       // V output (repurposed slot)
            b8 = resid;             // bv (repurposed slot)
            m0 = (blockIdx.x - 4) * 128; n0 = blockIdx.y * 128;
            Nout = HW; biasOnM = true;
        }
    } else {
        Ap = A + (size_t)bz * sA + (size_t)(blockIdx.y * 128) * K;
        Bp = B + (size_t)bz * sB + (size_t)(blockIdx.x * 128) * K;
        m0 = blockIdx.y * 128; n0 = blockIdx.x * 128;
        Nout = N;
    }

    const int tid = threadIdx.x, lane = tid & 31, warp = tid >> 5;
    const int wm = warp >> 2, wn = warp & 3;

    const unsigned smbase = (unsigned)__cvta_generic_to_shared(sm);

    const int lm = tid >> 2, lc = tid & 3;
    const bf16* gA0 = Ap + (size_t)(lm)      * K + lc * 8;
    const bf16* gA1 = Ap + (size_t)(lm + 64) * K + lc * 8;
    const bf16* gB0 = Bp + (size_t)(lm)      * K + lc * 8;
    const bf16* gB1 = Bp + (size_t)(lm + 64) * K + lc * 8;
    const unsigned dA0 = swz(lm, lc) * 16u;
    const unsigned dA1 = swz(lm + 64, lc) * 16u;
    const unsigned dB0 = 8192u + swz(lm, lc) * 16u;
    const unsigned dB1 = 8192u + swz(lm + 64, lc) * 16u;

    unsigned aOff[4], bOff[2];
    {
        int r = wm * 64 + (lane & 15);
        int c0 = lane >> 4;
        #pragma unroll
        for (int mt = 0; mt < 4; mt++) aOff[mt] = swz(r + mt * 16, c0) * 16u;
    }
    {
        int r = wn * 32 + ((lane >> 4) << 3) + (lane & 7);
        int c0 = (lane >> 3) & 1;
        #pragma unroll
        for (int p = 0; p < 2; p++) bOff[p] = 8192u + swz(r + p * 16, c0) * 16u;
    }

    float acc[4][4][4];
    #pragma unroll
    for (int i = 0; i < 4; i++)
        #pragma unroll
        for (int j = 0; j < 4; j++)
            #pragma unroll
            for (int r = 0; r < 4; r++) acc[i][j][r] = 0.f;

    const int iters = K >> 6;           // BK=64; K >= 256 -> iters >= 4 > STAGES-1

    // prologue: fill stages 0..STAGES-2 (each stage = two 32-col sub-chunks)
    #pragma unroll
    for (int s = 0; s < STAGES - 1; ++s) {
        unsigned st = smbase + (unsigned)s * STAGE_BYTES;
        #pragma unroll
        for (int sub = 0; sub < 2; ++sub) {
            unsigned sp = st + (unsigned)sub * 16384u;
            int k0 = (s * 2 + sub) << 5;
            CP16(sp + dA0, gA0 + k0); CP16(sp + dA1, gA1 + k0);
            CP16(sp + dB0, gB0 + k0); CP16(sp + dB1, gB1 + k0);
        }
        COMMIT();
    }

    int cs = 0;                                      // consuming stage index
    for (int it = 0; it < iters; ++it) {
        WAITG(STAGES - 2);
        __syncthreads();
        {
            int pf = it + STAGES - 1;
            if (pf < iters) {
                int fs = cs - 1; if (fs < 0) fs = STAGES - 1;
                unsigned st = smbase + (unsigned)fs * STAGE_BYTES;
                #pragma unroll
                for (int sub = 0; sub < 2; ++sub) {
                    unsigned sp = st + (unsigned)sub * 16384u;
                    int k0 = (pf * 2 + sub) << 5;
                    CP16(sp + dA0, gA0 + k0); CP16(sp + dA1, gA1 + k0);
                    CP16(sp + dB0, gB0 + k0); CP16(sp + dB1, gB1 + k0);
                }
            }
            COMMIT();
        }

        const unsigned sb0 = smbase + (unsigned)cs * STAGE_BYTES;
        #pragma unroll
        for (int sub = 0; sub < 2; ++sub) {
            const unsigned sb = sb0 + (unsigned)sub * 16384u;
            #pragma unroll
            for (int ks = 0; ks < 2; ++ks) {
                const unsigned kx = (unsigned)ks * 32u;
                unsigned a[4][4], b[2][4];
                #pragma unroll
                for (int mt = 0; mt < 4; mt++)
                    LDMX4(a[mt][0], a[mt][1], a[mt][2], a[mt][3], sb + (aOff[mt] ^ kx));
                #pragma unroll
                for (int p = 0; p < 2; p++)
                    LDMX4(b[p][0], b[p][1], b[p][2], b[p][3], sb + (bOff[p] ^ kx));

                #pragma unroll
                for (int mt = 0; mt < 4; mt++) {
                    #pragma unroll
                    for (int nt = 0; nt < 4; nt++) {
                        const int p = nt >> 1, h = (nt & 1) << 1;
                        MMA16816(acc[mt][nt][0], acc[mt][nt][1], acc[mt][nt][2], acc[mt][nt][3],
                                 a[mt][0], a[mt][1], a[mt][2], a[mt][3],
                                 b[p][h + 0], b[p][h + 1]);
                    }
                }
            }
        }
        if (++cs == STAGES) cs = 0;
    }

    // epilogue: c0 @(r,cc) c1 @(r,cc+1) c2 @(r+8,cc) c3 @(r+8,cc+1)
    const int row = m0 + wm * 64 + (lane >> 2);
    const int col = n0 + wn * 32 + (lane & 3) * 2;

    if (EPI == 4) {
        float* D = (float*)Dv + (size_t)bz * sD;
        const float* R = resid + (size_t)bz * sD;
        #pragma unroll
        for (int mt = 0; mt < 4; mt++) {
            #pragma unroll
            for (int nt = 0; nt < 4; nt++) {
                int r = row + mt * 16, cc = col + nt * 8;
                float b0 = bias[r], b1 = bias[r + 8];
                float2 v0 = { acc[mt][nt][0] + b0, acc[mt][nt][1] + b0 };
                float2 v1 = { acc[mt][nt][2] + b1, acc[mt][nt][3] + b1 };
                float2 r0 = *(const float2*)(&R[(size_t)r * Nout + cc]);
                float2 r1 = *(const float2*)(&R[(size_t)(r + 8) * Nout + cc]);
                v0.x += r0.x; v0.y += r0.y; v1.x += r1.x; v1.y += r1.y;
                *(float2*)(&D[(size_t)r * Nout + cc])       = v0;
                *(float2*)(&D[(size_t)(r + 8) * Nout + cc]) = v1;
            }
        }
    } else if (EPI == 5) {
        // exp epilogue + row-sum atomics (scores). M == HW, rows are i.
        bf16* D = (bf16*)Dv + (size_t)bz * sD;
        float* lrow = lptr + (size_t)bz * M;
        #pragma unroll
        for (int mt = 0; mt < 4; mt++) {
            const int r = row + mt * 16;
            float s0 = 0.f, s1 = 0.f;
            #pragma unroll
            for (int nt = 0; nt < 4; nt++) {
                int cc = col + nt * 8;
                float e0 = __expf(acc[mt][nt][0] * scale);
                float e1 = __expf(acc[mt][nt][1] * scale);
                float e2 = __expf(acc[mt][nt][2] * scale);
                float e3 = __expf(acc[mt][nt][3] * scale);
                s0 += e0 + e1;  s1 += e2 + e3;
                __nv_bfloat162 o0 = __floats2bfloat162_rn(e0, e1);
                __nv_bfloat162 o1 = __floats2bfloat162_rn(e2, e3);
                *(__nv_bfloat162*)(&D[(size_t)r * Nout + cc])       = o0;
                *(__nv_bfloat162*)(&D[(size_t)(r + 8) * Nout + cc]) = o1;
            }
            s0 += __shfl_xor_sync(0xffffffffu, s0, 1);
            s0 += __shfl_xor_sync(0xffffffffu, s0, 2);
            s1 += __shfl_xor_sync(0xffffffffu, s1, 1);
            s1 += __shfl_xor_sync(0xffffffffu, s1, 2);
            if ((lane & 3) == 0) {
                atomicAdd(&lrow[r],     s0);
                atomicAdd(&lrow[r + 8], s1);
            }
        }
    } else if (EPI == 6) {
        // divide-by-rowsum epilogue (attn). M == HW, rows are i.
        bf16* D = (bf16*)Dv + (size_t)bz * sD;
        const float* lrow = lptr + (size_t)bz * M;
        #pragma unroll
        for (int mt = 0; mt < 4; mt++) {
            const int r = row + mt * 16;
            const float inv0 = 1.0f / lrow[r];
            const float inv1 = 1.0f / lrow[r + 8];
            #pragma unroll
            for (int nt = 0; nt < 4; nt++) {
                int cc = col + nt * 8;
                __nv_bfloat162 o0 = __floats2bfloat162_rn(acc[mt][nt][0] * inv0,
                                                          acc[mt][nt][1] * inv0);
                __nv_bfloat162 o1 = __floats2bfloat162_rn(acc[mt][nt][2] * inv1,
                                                          acc[mt][nt][3] * inv1);
                *(__nv_bfloat162*)(&D[(size_t)r * Nout + cc])       = o0;
                *(__nv_bfloat162*)(&D[(size_t)(r + 8) * Nout + cc]) = o1;
            }
        }
    } else {
        // EPI 8: bias[n] (Q/K) or bias[m] (V)
        bf16* D = D8 + (size_t)bz * sD;
        #pragma unroll
        for (int mt = 0; mt < 4; mt++) {
            #pragma unroll
            for (int nt = 0; nt < 4; nt++) {
                int r = row + mt * 16, cc = col + nt * 8;
                float ax, ay, bx, by;
                if (biasOnM) {
                    float t0 = b8[r], t1 = b8[r + 8];
                    ax = t0; ay = t0; bx = t1; by = t1;
                } else {
                    float t0 = b8[cc], t1 = b8[cc + 1];
                    ax = t0; ay = t1; bx = t0; by = t1;
                }
                __nv_bfloat162 o0, o1;
                o0.x = __float2bfloat16_rn(acc[mt][nt][0] + ax);
                o0.y = __float2bfloat16_rn(acc[mt][nt][1] + ay);
                o1.x = __float2bfloat16_rn(acc[mt][nt][2] + bx);
                o1.y = __float2bfloat16_rn(acc[mt][nt][3] + by);
                *(__nv_bfloat162*)(&D[(size_t)r * Nout + cc])       = o0;
                *(__nv_bfloat162*)(&D[(size_t)(r + 8) * Nout + cc]) = o1;
            }
        }
    }
}

// ---------------- launch --------------------------------------------------------
extern "C" void kernel_launch(void* const* d_in, const int* in_sizes, int n_in,
                              void* d_out, int out_size) {
    const float* x  = (const float*)d_in[0];
    const float* gs = (const float*)d_in[1];
    const float* gb = (const float*)d_in[2];
    const float* wq = (const float*)d_in[3];
    const float* bq = (const float*)d_in[4];
    const float* wk = (const float*)d_in[5];
    const float* bk = (const float*)d_in[6];
    const float* wv = (const float*)d_in[7];
    const float* bv = (const float*)d_in[8];
    const float* wp = (const float*)d_in[9];
    const float* bp = (const float*)d_in[10];
    float* out = (float*)d_out;

    bf16 *p_ofT, *p_q, *p_k, *p_v, *p_atT, *p_s, *p_w16;
    float *p_l;
    cudaGetSymbolAddress((void**)&p_ofT, g_ofT);
    cudaGetSymbolAddress((void**)&p_q,   g_q);
    cudaGetSymbolAddress((void**)&p_k,   g_k);
    cudaGetSymbolAddress((void**)&p_v,   g_v);
    cudaGetSymbolAddress((void**)&p_atT, g_atT);
    cudaGetSymbolAddress((void**)&p_s,   g_s);
    cudaGetSymbolAddress((void**)&p_w16, g_w16);
    cudaGetSymbolAddress((void**)&p_l,   g_l);

    cudaFuncSetAttribute(mma_gemm<4>, cudaFuncAttributeMaxDynamicSharedMemorySize, GEMM_SMEM_BYTES);
    cudaFuncSetAttribute(mma_gemm<5>, cudaFuncAttributeMaxDynamicSharedMemorySize, GEMM_SMEM_BYTES);
    cudaFuncSetAttribute(mma_gemm<6>, cudaFuncAttributeMaxDynamicSharedMemorySize, GEMM_SMEM_BYTES);
    cudaFuncSetAttribute(mma_gemm<8>, cudaFuncAttributeMaxDynamicSharedMemorySize, GEMM_SMEM_BYTES);

    const long long sIC = (long long)HW * CH;   // [i][c] per-batch stride (== CH*HW)
    const long long sW  = (long long)HW * HW;

    // 1) conv_w (also zeroes g_l/g_sum/g_sum2) -> gn_stats -> gn_apply_t
    conv_w<<<CH * CH / 256, 256>>>(wq, wk, wv, wp);
    gn_stats<<<BATCH * NGROUP * 8, 256>>>(x);
    gn_apply_t<<<dim3(HW / 32, CH / 64, BATCH), 256>>>(x, gs, gb);

    // 2) Q, K, V fused in ONE launch (grid.x = 6: 0-3 -> Q/K, 4-5 -> V)
    dim3 gQKV(6, HW / 128, BATCH);
    mma_gemm<8><<<gQKV, 256, GEMM_SMEM_BYTES>>>(
        p_ofT, p_w16, p_q, HW, CH, CH, sIC, 0, sIC, 1.0f,
        bq, bv, (float*)p_v, p_k, bk);

    // 3) scores -> expS (bf16) + row sums l  (softmax without max-subtraction)
    dim3 gS(HW / 128, HW / 128, BATCH);
    mma_gemm<5><<<gS, 256, GEMM_SMEM_BYTES>>>(p_q, p_k, p_s, HW, HW, CH, sIC, sIC, sW, 0.0625f, nullptr, nullptr, p_l);

    // 4) attn (transposed): atT[i][c] = (1/l_i) * sum_j expS[i,j] V[c,j]
    dim3 gA(CH / 128, HW / 128, BATCH);
    mma_gemm<6><<<gA, 256, GEMM_SMEM_BYTES>>>(p_s, p_v, p_atT, HW, CH, HW, sW, sIC, sIC, 1.0f, nullptr, nullptr, p_l);

    // 5) proj + bias + residual -> d_out
    dim3 gP(HW / 128, CH / 128, BATCH);
    mma_gemm<4><<<gP, 256, GEMM_SMEM_BYTES>>>(p_w16 + 3 * CH * CH, p_atT, out, CH, HW, CH, 0, sIC, sIC, 1.0f, bp, x);
}

// round 15
// speedup vs baseline: 1.5644x; 1.0126x over previous
#include <cuda_runtime.h>
#include <cuda_bf16.h>
#include <math.h>
#include <stdint.h>

#define BATCH  4
#define CH     256
#define NGROUP 32
#define HW     4096
#define GEPS   1e-6f
#define STAGES 3
#define STAGE_BYTES 32768u

typedef __nv_bfloat16 bf16;

// ---------------- scratch (device globals; no allocation allowed) -------------
__device__ bf16  g_ofT[(size_t)BATCH * HW * CH];   // GN output, transposed [b][i][c]
__device__ bf16  g_q  [(size_t)BATCH * HW * CH];   // Q  [b][i][c]
__device__ bf16  g_k  [(size_t)BATCH * HW * CH];   // K  [b][j][c]
__device__ bf16  g_v  [(size_t)BATCH * CH * HW];   // V  [b][c][j]
__device__ bf16  g_atT[(size_t)BATCH * HW * CH];   // attn out transposed [b][i][c]
__device__ bf16  g_s  [(size_t)BATCH * HW * HW];   // expS bf16 (134MB)
__device__ bf16  g_w16[4 * CH * CH];               // bf16 weights: wq|wk|wv|wp
__device__ float g_l  [BATCH * HW];                // softmax row sums (atomic)
__device__ float g_part[BATCH * NGROUP * 16];      // GN partials: [bg][slice<8]=sum, [bg][8+slice]=sum2

// ---------------- prep: GN stats slices (no atomics) + weight conv + g_l zero ----
// grid.x = 1280: blocks 0..1023 -> stats (bg = blk>>3, slice = blk&7);
//                blocks 1024..1279 -> weight conversion + g_l zeroing.
__global__ void __launch_bounds__(256) prep(const float* __restrict__ x,
                                            const float* __restrict__ wq,
                                            const float* __restrict__ wk,
                                            const float* __restrict__ wv,
                                            const float* __restrict__ wp) {
    const int blk = blockIdx.x;
    const int tid = threadIdx.x;

    if (blk < 1024) {
        const int bg = blk >> 3, slice = blk & 7;
        const float* p = x + (size_t)bg * (CH / NGROUP) * HW + (size_t)slice * 4096;

        float s = 0.f, s2 = 0.f;
        #pragma unroll
        for (int i = 0; i < 4; i++) {                // 1024 float4 per slice
            float4 v = ((const float4*)p)[tid + i * 256];
            s  += v.x + v.y + v.z + v.w;
            s2 += v.x * v.x + v.y * v.y + v.z * v.z + v.w * v.w;
        }
        __shared__ float red[64];
        #pragma unroll
        for (int o = 16; o; o >>= 1) {
            s  += __shfl_xor_sync(0xffffffffu, s,  o);
            s2 += __shfl_xor_sync(0xffffffffu, s2, o);
        }
        if ((tid & 31) == 0) { red[tid >> 5] = s; red[32 + (tid >> 5)] = s2; }
        __syncthreads();
        if (tid == 0) {
            float ts = 0.f, ts2 = 0.f;
            #pragma unroll
            for (int w = 0; w < 8; w++) { ts += red[w]; ts2 += red[32 + w]; }
            g_part[bg * 16 + slice]     = ts;
            g_part[bg * 16 + 8 + slice] = ts2;
        }
    } else {
        int i = (blk - 1024) * 256 + tid;            // 0..65535
        if (i < BATCH * HW) g_l[i] = 0.f;
        g_w16[0 * CH * CH + i] = __float2bfloat16_rn(wq[i]);
        g_w16[1 * CH * CH + i] = __float2bfloat16_rn(wk[i]);
        g_w16[2 * CH * CH + i] = __float2bfloat16_rn(wv[i]);
        g_w16[3 * CH * CH + i] = __float2bfloat16_rn(wp[i]);
    }
}

// ---------------- GroupNorm apply + transpose -> bf16 OF^T [b][i][c] -----------
// 32i x 64c tiles; loads and stores both fully 128B-coalesced.
// mean/rstd reduced from g_part slots once per CTA (8 groups per 64-channel block).
__global__ void __launch_bounds__(256) gn_apply_t(const float* __restrict__ x,
                                                  const float* __restrict__ gs,
                                                  const float* __restrict__ gb) {
    __shared__ float tile[64][33];                   // [c_local][i_local]
    __shared__ float gmean[8], grstd[8];
    const int i0 = blockIdx.x * 32, c0 = blockIdx.y * 64, b = blockIdx.z;
    const int tid = threadIdx.x;
    const int il = tid & 31, cbase = tid >> 5;       // 8 c-rows per pass

    if (tid < 8) {
        const int bg = b * NGROUP + (c0 >> 3) + tid;
        float s = 0.f, s2 = 0.f;
        #pragma unroll
        for (int k = 0; k < 8; k++) { s += g_part[bg * 16 + k]; s2 += g_part[bg * 16 + 8 + k]; }
        const float inv_n = 1.0f / ((CH / NGROUP) * HW);
        float mean = s * inv_n;
        float var  = s2 * inv_n - mean * mean;
        gmean[tid] = mean;
        grstd[tid] = rsqrtf(var + GEPS);
    }
    __syncthreads();

    #pragma unroll
    for (int cc = 0; cc < 8; cc++) {
        int cl = cbase + cc * 8;                     // 0..63
        int c = c0 + cl;
        int g = cl >> 3;                             // group within this block
        float r = grstd[g];
        float a = gs[c] * r;
        float t = gb[c] - gmean[g] * a;
        float v = x[((size_t)b * CH + c) * HW + i0 + il];
        tile[cl][il] = v * a + t;
    }
    __syncthreads();

    #pragma unroll
    for (int h = 0; h < 4; h++) {
        int p = tid + h * 256;                       // 1024 bf162 slots
        int ir = p >> 5, cl = (p & 31) * 2;          // row 0..31, col 0..62
        __nv_bfloat162 o;
        o.x = __float2bfloat16_rn(tile[cl][ir]);
        o.y = __float2bfloat16_rn(tile[cl + 1][ir]);
        *(__nv_bfloat162*)(&g_ofT[((size_t)b * HW + i0 + ir) * CH + c0 + cl]) = o;
    }
}

// ---------------- bf16 tensor-core GEMM (mma.sync HMMA) -------------------------
// D[m][n] = scale * sum_k A[m][k]*B[n][k] (+ epilogue)
// A: [M][K] bf16 k-contig, B: [N][K] bf16 k-contig.
// EPI 4: fp32 out + bias[m] + resid[m][n].
// EPI 5: bf16 out = exp(acc*scale); atomicAdd per-row sums into lptr.
// EPI 6: bf16 out = acc / lptr[row].
// EPI 8: fused Q|K|V projection, grid.x = 6 (see R14).
// CTA 128x128, 8 warps (2m x 4n), warp tile 64x32, mma m16n8k16.
// Pipeline: BK=64 per stage, STAGES=3, one sync per 64-K.
// __launch_bounds__(256, 2) pins regs <= 128 so all variants keep 2 CTAs/SM.

__device__ __forceinline__ unsigned swz(int m, int c) {  // 16B-chunk index in [128][32]bf16 tile
    return (unsigned)((m << 2) + (c ^ ((m >> 1) & 3)));
}

#define CP16(dst_u32, src_ptr) \
    asm volatile("cp.async.cg.shared.global [%0], [%1], 16;\n" :: "r"(dst_u32), "l"(src_ptr))
#define LDMX4(r0, r1, r2, r3, addr) \
    asm volatile("ldmatrix.sync.aligned.m8n8.x4.shared.b16 {%0,%1,%2,%3}, [%4];\n" \
                 : "=r"(r0), "=r"(r1), "=r"(r2), "=r"(r3) : "r"(addr))
#define MMA16816(c0, c1, c2, c3, a0, a1, a2, a3, b0, b1) \
    asm volatile("mma.sync.aligned.m16n8k16.row.col.f32.bf16.bf16.f32 " \
                 "{%0,%1,%2,%3}, {%4,%5,%6,%7}, {%8,%9}, {%0,%1,%2,%3};\n" \
                 : "+f"(c0), "+f"(c1), "+f"(c2), "+f"(c3) \
                 : "r"(a0), "r"(a1), "r"(a2), "r"(a3), "r"(b0), "r"(b1))
#define COMMIT() asm volatile("cp.async.commit_group;\n")
#define WAITG(n) asm volatile("cp.async.wait_group %0;\n" :: "n"(n))

#define GEMM_SMEM_BYTES (STAGES * STAGE_BYTES)

template<int EPI>
__global__ void __launch_bounds__(256, 2) mma_gemm(
    const bf16* __restrict__ A, const bf16* __restrict__ B,
    void* __restrict__ Dv, int M, int N, int K,
    long long sA, long long sB, long long sD, float scale,
    const float* __restrict__ bias, const float* __restrict__ resid,
    float* __restrict__ lptr = nullptr,
    void* __restrict__ Dv2 = nullptr, const float* __restrict__ bias2 = nullptr)
{
    extern __shared__ __align__(16) unsigned char sm[];   // STAGES x [sub0: A|B, sub1: A|B]
    const int bz = blockIdx.z;

    const bf16 *Ap, *Bp;
    int m0, n0, Nout;
    bf16* D8 = nullptr; const float* b8 = nullptr; bool biasOnM = false;

    if (EPI == 8) {
        if (blockIdx.x < 4) {
            // Q/K: A=ofT rows i, B=wq|wk rows (bx*128)
            Ap = A + (size_t)bz * sA + (size_t)(blockIdx.y * 128) * K;
            Bp = B + (size_t)(blockIdx.x * 128) * K;
            D8 = (bf16*)((blockIdx.x >> 1) ? Dv2 : Dv);
            b8 = (blockIdx.x >> 1) ? bias2 : bias;
            m0 = blockIdx.y * 128; n0 = (blockIdx.x & 1) * 128;
            Nout = CH; biasOnM = false;
        } else {
            // V: A = wv rows c, B = ofT rows j
            Ap = B + (size_t)(2 * CH * CH) + (size_t)((blockIdx.x - 4) * 128) * K;
            Bp = A + (size_t)bz * sA + (size_t)(blockIdx.y * 128) * K;
            D8 = (bf16*)lptr;       // V output (repurposed slot)
            b8 = resid;             // bv (repurposed slot)
            m0 = (blockIdx.x - 4) * 128; n0 = blockIdx.y * 128;
            Nout = HW; biasOnM = true;
        }
    } else {
        Ap = A + (size_t)bz * sA + (size_t)(blockIdx.y * 128) * K;
        Bp = B + (size_t)bz * sB + (size_t)(blockIdx.x * 128) * K;
        m0 = blockIdx.y * 128; n0 = blockIdx.x * 128;
        Nout = N;
    }

    const int tid = threadIdx.x, lane = tid & 31, warp = tid >> 5;
    const int wm = warp >> 2, wn = warp & 3;

    const unsigned smbase = (unsigned)__cvta_generic_to_shared(sm);

    const int lm = tid >> 2, lc = tid & 3;
    const bf16* gA0 = Ap + (size_t)(lm)      * K + lc * 8;
    const bf16* gA1 = Ap + (size_t)(lm + 64) * K + lc * 8;
    const bf16* gB0 = Bp + (size_t)(lm)      * K + lc * 8;
    const bf16* gB1 = Bp + (size_t)(lm + 64) * K + lc * 8;
    const unsigned dA0 = swz(lm, lc) * 16u;
    const unsigned dA1 = swz(lm + 64, lc) * 16u;
    const unsigned dB0 = 8192u + swz(lm, lc) * 16u;
    const unsigned dB1 = 8192u + swz(lm + 64, lc) * 16u;

    unsigned aOff[4], bOff[2];
    {
        int r = wm * 64 + (lane & 15);
        int c0 = lane >> 4;
        #pragma unroll
        for (int mt = 0; mt < 4; mt++) aOff[mt] = swz(r + mt * 16, c0) * 16u;
    }
    {
        int r = wn * 32 + ((lane >> 4) << 3) + (lane & 7);
        int c0 = (lane >> 3) & 1;
        #pragma unroll
        for (int p = 0; p < 2; p++) bOff[p] = 8192u + swz(r + p * 16, c0) * 16u;
    }

    float acc[4][4][4];
    #pragma unroll
    for (int i = 0; i < 4; i++)
        #pragma unroll
        for (int j = 0; j < 4; j++)
            #pragma unroll
            for (int r = 0; r < 4; r++) acc[i][j][r] = 0.f;

    const int iters = K >> 6;           // BK=64; K >= 256 -> iters >= 4 > STAGES-1

    // prologue: fill stages 0..STAGES-2 (each stage = two 32-col sub-chunks)
    #pragma unroll
    for (int s = 0; s < STAGES - 1; ++s) {
        unsigned st = smbase + (unsigned)s * STAGE_BYTES;
        #pragma unroll
        for (int sub = 0; sub < 2; ++sub) {
            unsigned sp = st + (unsigned)sub * 16384u;
            int k0 = (s * 2 + sub) << 5;
            CP16(sp + dA0, gA0 + k0); CP16(sp + dA1, gA1 + k0);
            CP16(sp + dB0, gB0 + k0); CP16(sp + dB1, gB1 + k0);
        }
        COMMIT();
    }

    int cs = 0;                                      // consuming stage index
    for (int it = 0; it < iters; ++it) {
        WAITG(STAGES - 2);
        __syncthreads();
        {
            int pf = it + STAGES - 1;
            if (pf < iters) {
                int fs = cs - 1; if (fs < 0) fs = STAGES - 1;
                unsigned st = smbase + (unsigned)fs * STAGE_BYTES;
                #pragma unroll
                for (int sub = 0; sub < 2; ++sub) {
                    unsigned sp = st + (unsigned)sub * 16384u;
                    int k0 = (pf * 2 + sub) << 5;
                    CP16(sp + dA0, gA0 + k0); CP16(sp + dA1, gA1 + k0);
                    CP16(sp + dB0, gB0 + k0); CP16(sp + dB1, gB1 + k0);
                }
            }
            COMMIT();
        }

        const unsigned sb0 = smbase + (unsigned)cs * STAGE_BYTES;
        #pragma unroll
        for (int sub = 0; sub < 2; ++sub) {
            const unsigned sb = sb0 + (unsigned)sub * 16384u;
            #pragma unroll
            for (int ks = 0; ks < 2; ++ks) {
                const unsigned kx = (unsigned)ks * 32u;
                unsigned a[4][4], b[2][4];
                #pragma unroll
                for (int mt = 0; mt < 4; mt++)
                    LDMX4(a[mt][0], a[mt][1], a[mt][2], a[mt][3], sb + (aOff[mt] ^ kx));
                #pragma unroll
                for (int p = 0; p < 2; p++)
                    LDMX4(b[p][0], b[p][1], b[p][2], b[p][3], sb + (bOff[p] ^ kx));

                #pragma unroll
                for (int mt = 0; mt < 4; mt++) {
                    #pragma unroll
                    for (int nt = 0; nt < 4; nt++) {
                        const int p = nt >> 1, h = (nt & 1) << 1;
                        MMA16816(acc[mt][nt][0], acc[mt][nt][1], acc[mt][nt][2], acc[mt][nt][3],
                                 a[mt][0], a[mt][1], a[mt][2], a[mt][3],
                                 b[p][h + 0], b[p][h + 1]);
                    }
                }
            }
        }
        if (++cs == STAGES) cs = 0;
    }

    // epilogue: c0 @(r,cc) c1 @(r,cc+1) c2 @(r+8,cc) c3 @(r+8,cc+1)
    const int row = m0 + wm * 64 + (lane >> 2);
    const int col = n0 + wn * 32 + (lane & 3) * 2;

    if (EPI == 4) {
        float* D = (float*)Dv + (size_t)bz * sD;
        const float* R = resid + (size_t)bz * sD;
        #pragma unroll
        for (int mt = 0; mt < 4; mt++) {
            #pragma unroll
            for (int nt = 0; nt < 4; nt++) {
                int r = row + mt * 16, cc = col + nt * 8;
                float b0 = bias[r], b1 = bias[r + 8];
                float2 v0 = { acc[mt][nt][0] + b0, acc[mt][nt][1] + b0 };
                float2 v1 = { acc[mt][nt][2] + b1, acc[mt][nt][3] + b1 };
                float2 r0 = *(const float2*)(&R[(size_t)r * Nout + cc]);
                float2 r1 = *(const float2*)(&R[(size_t)(r + 8) * Nout + cc]);
                v0.x += r0.x; v0.y += r0.y; v1.x += r1.x; v1.y += r1.y;
                *(float2*)(&D[(size_t)r * Nout + cc])       = v0;
                *(float2*)(&D[(size_t)(r + 8) * Nout + cc]) = v1;
            }
        }
    } else if (EPI == 5) {
        // exp epilogue + row-sum atomics (scores). M == HW, rows are i.
        bf16* D = (bf16*)Dv + (size_t)bz * sD;
        float* lrow = lptr + (size_t)bz * M;
        #pragma unroll
        for (int mt = 0; mt < 4; mt++) {
            const int r = row + mt * 16;
            float s0 = 0.f, s1 = 0.f;
            #pragma unroll
            for (int nt = 0; nt < 4; nt++) {
                int cc = col + nt * 8;
                float e0 = __expf(acc[mt][nt][0] * scale);
                float e1 = __expf(acc[mt][nt][1] * scale);
                float e2 = __expf(acc[mt][nt][2] * scale);
                float e3 = __expf(acc[mt][nt][3] * scale);
                s0 += e0 + e1;  s1 += e2 + e3;
                __nv_bfloat162 o0 = __floats2bfloat162_rn(e0, e1);
                __nv_bfloat162 o1 = __floats2bfloat162_rn(e2, e3);
                *(__nv_bfloat162*)(&D[(size_t)r * Nout + cc])       = o0;
                *(__nv_bfloat162*)(&D[(size_t)(r + 8) * Nout + cc]) = o1;
            }
            s0 += __shfl_xor_sync(0xffffffffu, s0, 1);
            s0 += __shfl_xor_sync(0xffffffffu, s0, 2);
            s1 += __shfl_xor_sync(0xffffffffu, s1, 1);
            s1 += __shfl_xor_sync(0xffffffffu, s1, 2);
            if ((lane & 3) == 0) {
                atomicAdd(&lrow[r],     s0);
                atomicAdd(&lrow[r + 8], s1);
            }
        }
    } else if (EPI == 6) {
        // divide-by-rowsum epilogue (attn). M == HW, rows are i.
        bf16* D = (bf16*)Dv + (size_t)bz * sD;
        const float* lrow = lptr + (size_t)bz * M;
        #pragma unroll
        for (int mt = 0; mt < 4; mt++) {
            const int r = row + mt * 16;
            const float inv0 = 1.0f / lrow[r];
            const float inv1 = 1.0f / lrow[r + 8];
            #pragma unroll
            for (int nt = 0; nt < 4; nt++) {
                int cc = col + nt * 8;
                __nv_bfloat162 o0 = __floats2bfloat162_rn(acc[mt][nt][0] * inv0,
                                                          acc[mt][nt][1] * inv0);
                __nv_bfloat162 o1 = __floats2bfloat162_rn(acc[mt][nt][2] * inv1,
                                                          acc[mt][nt][3] * inv1);
                *(__nv_bfloat162*)(&D[(size_t)r * Nout + cc])       = o0;
                *(__nv_bfloat162*)(&D[(size_t)(r + 8) * Nout + cc]) = o1;
            }
        }
    } else {
        // EPI 8: bias[n] (Q/K) or bias[m] (V)
        bf16* D = D8 + (size_t)bz * sD;
        #pragma unroll
        for (int mt = 0; mt < 4; mt++) {
            #pragma unroll
            for (int nt = 0; nt < 4; nt++) {
                int r = row + mt * 16, cc = col + nt * 8;
                float ax, ay, bx, by;
                if (biasOnM) {
                    float t0 = b8[r], t1 = b8[r + 8];
                    ax = t0; ay = t0; bx = t1; by = t1;
                } else {
                    float t0 = b8[cc], t1 = b8[cc + 1];
                    ax = t0; ay = t1; bx = t0; by = t1;
                }
                __nv_bfloat162 o0, o1;
                o0.x = __float2bfloat16_rn(acc[mt][nt][0] + ax);
                o0.y = __float2bfloat16_rn(acc[mt][nt][1] + ay);
                o1.x = __float2bfloat16_rn(acc[mt][nt][2] + bx);
                o1.y = __float2bfloat16_rn(acc[mt][nt][3] + by);
                *(__nv_bfloat162*)(&D[(size_t)r * Nout + cc])       = o0;
                *(__nv_bfloat162*)(&D[(size_t)(r + 8) * Nout + cc]) = o1;
            }
        }
    }
}

// ---------------- launch --------------------------------------------------------
extern "C" void kernel_launch(void* const* d_in, const int* in_sizes, int n_in,
                              void* d_out, int out_size) {
    const float* x  = (const float*)d_in[0];
    const float* gs = (const float*)d_in[1];
    const float* gb = (const float*)d_in[2];
    const float* wq = (const float*)d_in[3];
    const float* bq = (const float*)d_in[4];
    const float* wk = (const float*)d_in[5];
    const float* bk = (const float*)d_in[6];
    const float* wv = (const float*)d_in[7];
    const float* bv = (const float*)d_in[8];
    const float* wp = (const float*)d_in[9];
    const float* bp = (const float*)d_in[10];
    float* out = (float*)d_out;

    bf16 *p_ofT, *p_q, *p_k, *p_v, *p_atT, *p_s, *p_w16;
    float *p_l;
    cudaGetSymbolAddress((void**)&p_ofT, g_ofT);
    cudaGetSymbolAddress((void**)&p_q,   g_q);
    cudaGetSymbolAddress((void**)&p_k,   g_k);
    cudaGetSymbolAddress((void**)&p_v,   g_v);
    cudaGetSymbolAddress((void**)&p_atT, g_atT);
    cudaGetSymbolAddress((void**)&p_s,   g_s);
    cudaGetSymbolAddress((void**)&p_w16, g_w16);
    cudaGetSymbolAddress((void**)&p_l,   g_l);

    cudaFuncSetAttribute(mma_gemm<4>, cudaFuncAttributeMaxDynamicSharedMemorySize, GEMM_SMEM_BYTES);
    cudaFuncSetAttribute(mma_gemm<5>, cudaFuncAttributeMaxDynamicSharedMemorySize, GEMM_SMEM_BYTES);
    cudaFuncSetAttribute(mma_gemm<6>, cudaFuncAttributeMaxDynamicSharedMemorySize, GEMM_SMEM_BYTES);
    cudaFuncSetAttribute(mma_gemm<8>, cudaFuncAttributeMaxDynamicSharedMemorySize, GEMM_SMEM_BYTES);

    const long long sIC = (long long)HW * CH;   // [i][c] per-batch stride (== CH*HW)
    const long long sW  = (long long)HW * HW;

    // 1) prep (GN stats slices + weight conversion + g_l zero) -> gn_apply_t
    prep<<<1280, 256>>>(x, wq, wk, wv, wp);
    gn_apply_t<<<dim3(HW / 32, CH / 64, BATCH), 256>>>(x, gs, gb);

    // 2) Q, K, V fused in ONE launch (grid.x = 6: 0-3 -> Q/K, 4-5 -> V)
    dim3 gQKV(6, HW / 128, BATCH);
    mma_gemm<8><<<gQKV, 256, GEMM_SMEM_BYTES>>>(
        p_ofT, p_w16, p_q, HW, CH, CH, sIC, 0, sIC, 1.0f,
        bq, bv, (float*)p_v, p_k, bk);

    // 3) scores -> expS (bf16) + row sums l  (softmax without max-subtraction)
    dim3 gS(HW / 128, HW / 128, BATCH);
    mma_gemm<5><<<gS, 256, GEMM_SMEM_BYTES>>>(p_q, p_k, p_s, HW, HW, CH, sIC, sIC, sW, 0.0625f, nullptr, nullptr, p_l);

    // 4) attn (transposed): atT[i][c] = (1/l_i) * sum_j expS[i,j] V[c,j]
    dim3 gA(CH / 128, HW / 128, BATCH);
    mma_gemm<6><<<gA, 256, GEMM_SMEM_BYTES>>>(p_s, p_v, p_atT, HW, CH, HW, sW, sIC, sIC, 1.0f, nullptr, nullptr, p_l);

    // 5) proj + bias + residual -> d_out
    dim3 gP(HW / 128, CH / 128, BATCH);
    mma_gemm<4><<<gP, 256, GEMM_SMEM_BYTES>>>(p_w16 + 3 * CH * CH, p_atT, out, CH, HW, CH, 0, sIC, sIC, 1.0f, bp, x);
}